// round 4
// baseline (speedup 1.0000x reference)
#include <cuda_runtime.h>
#include <cuda_bf16.h>
#include <math.h>
#include <stdint.h>

#define NN 50000
#define EE 800000
#define DD 256
#define HC 256          // H*C = 4*64
#define LL 3
#define SCALE 0.125f    // 1/sqrt(64)

// ---------------- scratch (static device globals; no allocation) -------------
__device__ float g_qkvs[NN * 1024];   // per node: [q(256) | k(256) | v(256) | s(256)]
__device__ float g_hA[NN * HC];
__device__ float g_hB[NN * HC];
__device__ int   g_rowptr[NN + 1];
__device__ int   g_cnt[NN];
__device__ int   g_offs[NN];
__device__ int   g_col[EE];

// ---------------- CSR construction ------------------------------------------
__global__ void zero_counts_kernel() {
    int i = blockIdx.x * blockDim.x + threadIdx.x;
    if (i < NN) { g_cnt[i] = 0; g_offs[i] = 0; }
}

__global__ void count_dst_kernel(const int* __restrict__ edge_index) {
    int e = blockIdx.x * blockDim.x + threadIdx.x;
    if (e < EE) {
        int d = edge_index[EE + e];   // dst row
        atomicAdd(&g_cnt[d], 1);
    }
}

// single-block exclusive scan over g_cnt -> g_rowptr
__global__ void exscan_kernel() {
    __shared__ int warpsum[32];
    __shared__ int carry_s;
    int tid = threadIdx.x, lane = tid & 31, wid = tid >> 5;
    if (tid == 0) carry_s = 0;
    __syncthreads();
    for (int base = 0; base < NN; base += 1024) {
        int i = base + tid;
        int val = (i < NN) ? g_cnt[i] : 0;
        int x = val;
        #pragma unroll
        for (int off = 1; off < 32; off <<= 1) {
            int y = __shfl_up_sync(0xffffffff, x, off);
            if (lane >= off) x += y;
        }
        if (lane == 31) warpsum[wid] = x;
        __syncthreads();
        if (wid == 0) {
            int w = warpsum[lane];
            #pragma unroll
            for (int off = 1; off < 32; off <<= 1) {
                int y = __shfl_up_sync(0xffffffff, w, off);
                if (lane >= off) w += y;
            }
            warpsum[lane] = w;
        }
        __syncthreads();
        int incl = x + (wid > 0 ? warpsum[wid - 1] : 0);
        int c = carry_s;
        if (i < NN) g_rowptr[i] = c + incl - val;  // exclusive
        __syncthreads();
        if (tid == 1023) carry_s = c + incl;
        __syncthreads();
    }
    if (tid == 0) g_rowptr[NN] = carry_s;
}

__global__ void fill_csr_kernel(const int* __restrict__ edge_index) {
    int e = blockIdx.x * blockDim.x + threadIdx.x;
    if (e < EE) {
        int s = edge_index[e];        // src
        int d = edge_index[EE + e];   // dst
        int pos = g_rowptr[d] + atomicAdd(&g_offs[d], 1);
        g_col[pos] = s;
    }
}

// ---------------- fused TF32 GEMM: [q|k|v|s] = A@{Wq,Wk,Wv,Ws} + bias --------
#define BM 128
#define BN 128
#define BK 16
#define ASTRIDE 20
#define BSTRIDE 136

__device__ __forceinline__ uint32_t f2tf32(float f) {
    uint32_t r;
    asm("cvt.rna.tf32.f32 %0, %1;" : "=r"(r) : "f"(f));
    return r;
}

__global__ __launch_bounds__(256, 2)
void gemm_qkvs_kernel(const float* __restrict__ A,
                      const float* __restrict__ W0, const float* __restrict__ W1,
                      const float* __restrict__ W2, const float* __restrict__ W3,
                      const float* __restrict__ b0, const float* __restrict__ b1,
                      const float* __restrict__ b2, const float* __restrict__ b3,
                      float* __restrict__ C, int M) {
    __shared__ uint32_t sA[2][BM * ASTRIDE];   // [m][k] stride 20
    __shared__ uint32_t sB[2][BK * BSTRIDE];   // [k][n] stride 136

    const int which = blockIdx.x >> 1;
    const float* B    = (which == 0) ? W0 : (which == 1) ? W1 : (which == 2) ? W2 : W3;
    const float* bias = (which == 0) ? b0 : (which == 1) ? b1 : (which == 2) ? b2 : b3;

    const int tid  = threadIdx.x;
    const int lane = tid & 31;
    const int wid  = tid >> 5;
    const int wm   = (wid & 3) * 32;
    const int wn   = (wid >> 2) * 64;
    const int brow = blockIdx.y * BM;
    const int bcol = (blockIdx.x & 1) * BN;

    float c[2][8][4];
    #pragma unroll
    for (int i = 0; i < 2; i++)
        #pragma unroll
        for (int j = 0; j < 8; j++)
            #pragma unroll
            for (int r = 0; r < 4; r++) c[i][j][r] = 0.f;

    int arow[2], akf[2], bkr[2], bnf[2];
    const float* aptr[2];
    const float* bptr0[2];
    #pragma unroll
    for (int i = 0; i < 2; i++) {
        int idx = tid + i * 256;
        arow[i] = idx >> 2;  akf[i] = (idx & 3) * 4;
        bkr[i]  = idx >> 5;  bnf[i] = (idx & 31) * 4;
        int gr = brow + arow[i];
        if (gr >= M) gr = M - 1;
        aptr[i]  = A + (size_t)gr * 256 + akf[i];
        bptr0[i] = B + (size_t)bkr[i] * 256 + bcol + bnf[i];
    }

    #pragma unroll
    for (int i = 0; i < 2; i++) {
        float4 av = *(const float4*)(aptr[i]);
        uint32_t* d = &sA[0][arow[i] * ASTRIDE + akf[i]];
        d[0] = f2tf32(av.x); d[1] = f2tf32(av.y);
        d[2] = f2tf32(av.z); d[3] = f2tf32(av.w);
        float4 bv = *(const float4*)(bptr0[i]);
        uint32_t* e = &sB[0][bkr[i] * BSTRIDE + bnf[i]];
        e[0] = f2tf32(bv.x); e[1] = f2tf32(bv.y);
        e[2] = f2tf32(bv.z); e[3] = f2tf32(bv.w);
    }
    __syncthreads();

    const int NSTEP = 256 / BK;   // 16
    float4 pa[2], pb[2];

    for (int t = 0; t < NSTEP; t++) {
        const int cur = t & 1;
        const bool has_next = (t + 1 < NSTEP);
        if (has_next) {
            int k0 = (t + 1) * BK;
            #pragma unroll
            for (int i = 0; i < 2; i++) {
                pa[i] = *(const float4*)(aptr[i] + k0);
                pb[i] = *(const float4*)(bptr0[i] + (size_t)k0 * 256);
            }
        }

        const uint32_t* __restrict__ sa = sA[cur];
        const uint32_t* __restrict__ sb = sB[cur];
        const int l4 = lane & 3, l8 = lane >> 2;

        #pragma unroll
        for (int kb = 0; kb < BK; kb += 8) {
            uint32_t af[2][4];
            #pragma unroll
            for (int mt = 0; mt < 2; mt++) {
                int mrow = wm + mt * 16 + l8;
                const uint32_t* p = &sa[mrow * ASTRIDE + kb + l4];
                af[mt][0] = p[0];
                af[mt][1] = p[8 * ASTRIDE];
                af[mt][2] = p[4];
                af[mt][3] = p[8 * ASTRIDE + 4];
            }
            uint32_t bf[8][2];
            #pragma unroll
            for (int nt = 0; nt < 8; nt++) {
                const uint32_t* p = &sb[(kb + l4) * BSTRIDE + wn + nt * 8 + l8];
                bf[nt][0] = p[0];
                bf[nt][1] = p[4 * BSTRIDE];
            }
            #pragma unroll
            for (int mt = 0; mt < 2; mt++)
                #pragma unroll
                for (int nt = 0; nt < 8; nt++) {
                    asm volatile(
                        "mma.sync.aligned.m16n8k8.row.col.f32.tf32.tf32.f32 "
                        "{%0,%1,%2,%3}, {%4,%5,%6,%7}, {%8,%9}, {%0,%1,%2,%3};"
                        : "+f"(c[mt][nt][0]), "+f"(c[mt][nt][1]),
                          "+f"(c[mt][nt][2]), "+f"(c[mt][nt][3])
                        : "r"(af[mt][0]), "r"(af[mt][1]),
                          "r"(af[mt][2]), "r"(af[mt][3]),
                          "r"(bf[nt][0]), "r"(bf[nt][1]));
                }
        }

        if (has_next) {
            const int nxt = cur ^ 1;
            #pragma unroll
            for (int i = 0; i < 2; i++) {
                uint32_t* d = &sA[nxt][arow[i] * ASTRIDE + akf[i]];
                d[0] = f2tf32(pa[i].x); d[1] = f2tf32(pa[i].y);
                d[2] = f2tf32(pa[i].z); d[3] = f2tf32(pa[i].w);
                uint32_t* e = &sB[nxt][bkr[i] * BSTRIDE + bnf[i]];
                e[0] = f2tf32(pb[i].x); e[1] = f2tf32(pb[i].y);
                e[2] = f2tf32(pb[i].z); e[3] = f2tf32(pb[i].w);
            }
        }
        __syncthreads();
    }

    const int l4 = lane & 3, l8 = lane >> 2;
    float* Cb = C + (size_t)which * 256;
    #pragma unroll
    for (int mt = 0; mt < 2; mt++) {
        #pragma unroll
        for (int half = 0; half < 2; half++) {
            int grow = brow + wm + mt * 16 + l8 + half * 8;
            if (grow < M) {
                #pragma unroll
                for (int nt = 0; nt < 8; nt++) {
                    int gcol = bcol + wn + nt * 8 + 2 * l4;
                    float2 o;
                    o.x = c[mt][nt][half * 2 + 0] + bias[gcol + 0];
                    o.y = c[mt][nt][half * 2 + 1] + bias[gcol + 1];
                    *(float2*)(Cb + (size_t)grow * 1024 + gcol) = o;
                }
            }
        }
    }
}

// ---------------- edge attention: one warp per node, PLAIN-exp softmax -------
// softmax(a) == exp(a)/sum(exp(a)) — max subtraction is mathematically a no-op
// and the logits here are tiny (|a| ~< 15 << 88), so drop the online-max
// rescale chain entirely. Accumulation is fully independent across edges:
// 4-edge unroll, 16 float4 gathers in flight per iteration.
__global__ void edge_attn_kernel(const float* __restrict__ qkvs,
                                 float* __restrict__ out) {
    int warp = (blockIdx.x * blockDim.x + threadIdx.x) >> 5;
    if (warp >= NN) return;
    int lane = threadIdx.x & 31;
    const int ch = lane * 8;
    const float* nb = qkvs + (size_t)warp * 1024;

    float4 q0 = *(const float4*)(nb + ch);
    float4 q1 = *(const float4*)(nb + ch + 4);

    float d = 0.f;
    float acc[8];
    #pragma unroll
    for (int i = 0; i < 8; i++) acc[i] = 0.f;

    const int e0 = g_rowptr[warp], e1 = g_rowptr[warp + 1];
    int e = e0;

    for (; e + 3 < e1; e += 4) {
        int s0 = g_col[e], s1 = g_col[e + 1], s2 = g_col[e + 2], s3 = g_col[e + 3];
        const float* kp0 = qkvs + (size_t)s0 * 1024 + 256 + ch;
        const float* kp1 = qkvs + (size_t)s1 * 1024 + 256 + ch;
        const float* kp2 = qkvs + (size_t)s2 * 1024 + 256 + ch;
        const float* kp3 = qkvs + (size_t)s3 * 1024 + 256 + ch;
        float4 ka0 = *(const float4*)kp0, ka1 = *(const float4*)(kp0 + 4);
        float4 kb0 = *(const float4*)kp1, kb1 = *(const float4*)(kp1 + 4);
        float4 kc0 = *(const float4*)kp2, kc1 = *(const float4*)(kp2 + 4);
        float4 kd0 = *(const float4*)kp3, kd1 = *(const float4*)(kp3 + 4);
        float4 va0 = *(const float4*)(kp0 + 256), va1 = *(const float4*)(kp0 + 260);
        float4 vb0 = *(const float4*)(kp1 + 256), vb1 = *(const float4*)(kp1 + 260);
        float4 vc0 = *(const float4*)(kp2 + 256), vc1 = *(const float4*)(kp2 + 260);
        float4 vd0 = *(const float4*)(kp3 + 256), vd1 = *(const float4*)(kp3 + 260);

        float p0 = q0.x*ka0.x + q0.y*ka0.y + q0.z*ka0.z + q0.w*ka0.w
                 + q1.x*ka1.x + q1.y*ka1.y + q1.z*ka1.z + q1.w*ka1.w;
        float p1 = q0.x*kb0.x + q0.y*kb0.y + q0.z*kb0.z + q0.w*kb0.w
                 + q1.x*kb1.x + q1.y*kb1.y + q1.z*kb1.z + q1.w*kb1.w;
        float p2 = q0.x*kc0.x + q0.y*kc0.y + q0.z*kc0.z + q0.w*kc0.w
                 + q1.x*kc1.x + q1.y*kc1.y + q1.z*kc1.z + q1.w*kc1.w;
        float p3 = q0.x*kd0.x + q0.y*kd0.y + q0.z*kd0.z + q0.w*kd0.w
                 + q1.x*kd1.x + q1.y*kd1.y + q1.z*kd1.z + q1.w*kd1.w;
        p0 += __shfl_xor_sync(0xffffffff, p0, 1);
        p1 += __shfl_xor_sync(0xffffffff, p1, 1);
        p2 += __shfl_xor_sync(0xffffffff, p2, 1);
        p3 += __shfl_xor_sync(0xffffffff, p3, 1);
        p0 += __shfl_xor_sync(0xffffffff, p0, 2);
        p1 += __shfl_xor_sync(0xffffffff, p1, 2);
        p2 += __shfl_xor_sync(0xffffffff, p2, 2);
        p3 += __shfl_xor_sync(0xffffffff, p3, 2);
        p0 += __shfl_xor_sync(0xffffffff, p0, 4);
        p1 += __shfl_xor_sync(0xffffffff, p1, 4);
        p2 += __shfl_xor_sync(0xffffffff, p2, 4);
        p3 += __shfl_xor_sync(0xffffffff, p3, 4);

        float pe0 = __expf(fminf(p0 * SCALE, 85.f));
        float pe1 = __expf(fminf(p1 * SCALE, 85.f));
        float pe2 = __expf(fminf(p2 * SCALE, 85.f));
        float pe3 = __expf(fminf(p3 * SCALE, 85.f));
        d += pe0 + pe1 + pe2 + pe3;
        acc[0] += pe0*va0.x + pe1*vb0.x + pe2*vc0.x + pe3*vd0.x;
        acc[1] += pe0*va0.y + pe1*vb0.y + pe2*vc0.y + pe3*vd0.y;
        acc[2] += pe0*va0.z + pe1*vb0.z + pe2*vc0.z + pe3*vd0.z;
        acc[3] += pe0*va0.w + pe1*vb0.w + pe2*vc0.w + pe3*vd0.w;
        acc[4] += pe0*va1.x + pe1*vb1.x + pe2*vc1.x + pe3*vd1.x;
        acc[5] += pe0*va1.y + pe1*vb1.y + pe2*vc1.y + pe3*vd1.y;
        acc[6] += pe0*va1.z + pe1*vb1.z + pe2*vc1.z + pe3*vd1.z;
        acc[7] += pe0*va1.w + pe1*vb1.w + pe2*vc1.w + pe3*vd1.w;
    }

    for (; e < e1; e++) {
        int s0 = g_col[e];
        const float* kp = qkvs + (size_t)s0 * 1024 + 256 + ch;
        float4 ka0 = *(const float4*)kp, ka1 = *(const float4*)(kp + 4);
        float4 va0 = *(const float4*)(kp + 256), va1 = *(const float4*)(kp + 260);
        float p = q0.x*ka0.x + q0.y*ka0.y + q0.z*ka0.z + q0.w*ka0.w
                + q1.x*ka1.x + q1.y*ka1.y + q1.z*ka1.z + q1.w*ka1.w;
        p += __shfl_xor_sync(0xffffffff, p, 1);
        p += __shfl_xor_sync(0xffffffff, p, 2);
        p += __shfl_xor_sync(0xffffffff, p, 4);
        float pe = __expf(fminf(p * SCALE, 85.f));
        d += pe;
        acc[0] += pe * va0.x;
        acc[1] += pe * va0.y;
        acc[2] += pe * va0.z;
        acc[3] += pe * va0.w;
        acc[4] += pe * va1.x;
        acc[5] += pe * va1.y;
        acc[6] += pe * va1.z;
        acc[7] += pe * va1.w;
    }

    float inv = (d > 0.f) ? 1.f / d : 0.f;
    const float* sp = nb + 768 + ch;
    float4 s0v = *(const float4*)sp;
    float4 s1v = *(const float4*)(sp + 4);
    float4 o0, o1;
    o0.x = fmaxf(acc[0] * inv + s0v.x, 0.f);
    o0.y = fmaxf(acc[1] * inv + s0v.y, 0.f);
    o0.z = fmaxf(acc[2] * inv + s0v.z, 0.f);
    o0.w = fmaxf(acc[3] * inv + s0v.w, 0.f);
    o1.x = fmaxf(acc[4] * inv + s1v.x, 0.f);
    o1.y = fmaxf(acc[5] * inv + s1v.y, 0.f);
    o1.z = fmaxf(acc[6] * inv + s1v.z, 0.f);
    o1.w = fmaxf(acc[7] * inv + s1v.w, 0.f);
    float* op = out + (size_t)warp * 256 + ch;
    *(float4*)op       = o0;
    *(float4*)(op + 4) = o1;
}

// ---------------- launch ------------------------------------------------------
extern "C" void kernel_launch(void* const* d_in, const int* in_sizes, int n_in,
                              void* d_out, int out_size) {
    const float* x   = (const float*)d_in[0];
    const int*   ei  = (const int*)d_in[1];
    const float* Wq  = (const float*)d_in[2];
    const float* bq  = (const float*)d_in[3];
    const float* Wk  = (const float*)d_in[4];
    const float* bk  = (const float*)d_in[5];
    const float* Wv  = (const float*)d_in[6];
    const float* bv  = (const float*)d_in[7];
    const float* Ws  = (const float*)d_in[8];
    const float* bs  = (const float*)d_in[9];
    float* out = (float*)d_out;

    float *qkvs, *hA, *hB;
    cudaGetSymbolAddress((void**)&qkvs, g_qkvs);
    cudaGetSymbolAddress((void**)&hA,   g_hA);
    cudaGetSymbolAddress((void**)&hB,   g_hB);

    zero_counts_kernel<<<(NN + 255) / 256, 256>>>();
    count_dst_kernel<<<(EE + 255) / 256, 256>>>(ei);
    exscan_kernel<<<1, 1024>>>();
    fill_csr_kernel<<<(EE + 255) / 256, 256>>>(ei);

    dim3 gemm_grid(8, (NN + BM - 1) / BM);
    int edge_blocks = (NN + 7) / 8;

    const float* hin = x;
    for (int l = 0; l < LL; l++) {
        size_t wo = (size_t)l * DD * HC;
        gemm_qkvs_kernel<<<gemm_grid, 256>>>(
            hin,
            Wq + wo, Wk + wo, Wv + wo, Ws + wo,
            bq + l * HC, bk + l * HC, bv + l * HC, bs + l * HC,
            qkvs, NN);

        float* hout = (l == LL - 1) ? out : ((l == 0) ? hA : hB);
        edge_attn_kernel<<<edge_blocks, 256>>>(qkvs, hout);
        hin = hout;
    }
}

// round 5
// speedup vs baseline: 1.2522x; 1.2522x over previous
#include <cuda_runtime.h>
#include <cuda_fp16.h>
#include <math.h>
#include <stdint.h>

#define NN 50000
#define EE 800000
#define DD 256
#define HC 256          // H*C = 4*64
#define LL 3
#define SCALE 0.125f    // 1/sqrt(64)

// ---------------- scratch (static device globals; no allocation) -------------
__device__ float g_qkvs[NN * 1024];   // per node: [q(256) | k(256) | v(256) | s(256)]
__device__ float g_hA[NN * HC];
__device__ float g_hB[NN * HC];
__device__ int   g_rowptr[NN + 1];
__device__ int   g_cnt[NN];
__device__ int   g_offs[NN];
__device__ int   g_col[EE];

// ---------------- CSR construction ------------------------------------------
__global__ void zero_counts_kernel() {
    int i = blockIdx.x * blockDim.x + threadIdx.x;
    if (i < NN) { g_cnt[i] = 0; g_offs[i] = 0; }
}

__global__ void count_dst_kernel(const int* __restrict__ edge_index) {
    int e = blockIdx.x * blockDim.x + threadIdx.x;
    if (e < EE) {
        int d = edge_index[EE + e];
        atomicAdd(&g_cnt[d], 1);
    }
}

__global__ void exscan_kernel() {
    __shared__ int warpsum[32];
    __shared__ int carry_s;
    int tid = threadIdx.x, lane = tid & 31, wid = tid >> 5;
    if (tid == 0) carry_s = 0;
    __syncthreads();
    for (int base = 0; base < NN; base += 1024) {
        int i = base + tid;
        int val = (i < NN) ? g_cnt[i] : 0;
        int x = val;
        #pragma unroll
        for (int off = 1; off < 32; off <<= 1) {
            int y = __shfl_up_sync(0xffffffff, x, off);
            if (lane >= off) x += y;
        }
        if (lane == 31) warpsum[wid] = x;
        __syncthreads();
        if (wid == 0) {
            int w = warpsum[lane];
            #pragma unroll
            for (int off = 1; off < 32; off <<= 1) {
                int y = __shfl_up_sync(0xffffffff, w, off);
                if (lane >= off) w += y;
            }
            warpsum[lane] = w;
        }
        __syncthreads();
        int incl = x + (wid > 0 ? warpsum[wid - 1] : 0);
        int c = carry_s;
        if (i < NN) g_rowptr[i] = c + incl - val;
        __syncthreads();
        if (tid == 1023) carry_s = c + incl;
        __syncthreads();
    }
    if (tid == 0) g_rowptr[NN] = carry_s;
}

__global__ void fill_csr_kernel(const int* __restrict__ edge_index) {
    int e = blockIdx.x * blockDim.x + threadIdx.x;
    if (e < EE) {
        int s = edge_index[e];
        int d = edge_index[EE + e];
        int pos = g_rowptr[d] + atomicAdd(&g_offs[d], 1);
        g_col[pos] = s;
    }
}

// ---------------- fused FP16 GEMM: [q|k|v|s] = A@{Wq,Wk,Wv,Ws} + bias --------
// 128x128 block tile, BK=16, 8 warps (32x64 warp tile), mma.m16n8k16.f16,
// fp32 accumulate. ldmatrix x4 (A) / x4.trans (B) fragment loads.
#define BM 128
#define BN 128
#define BK 16
#define ASTR 24     // halfs per A row (16 + 8 pad): ldmatrix chunks bank 12r%32 distinct
#define BSTR 136    // halfs per B row (128 + 8 pad): ldmatrix chunks bank 4k%32 distinct

__device__ __forceinline__ uint2 pack4h(float4 v) {
    __half2 a = __floats2half2_rn(v.x, v.y);
    __half2 b = __floats2half2_rn(v.z, v.w);
    uint2 r;
    r.x = *(uint32_t*)&a;
    r.y = *(uint32_t*)&b;
    return r;
}

__global__ __launch_bounds__(256, 2)
void gemm_qkvs_kernel(const float* __restrict__ A,
                      const float* __restrict__ W0, const float* __restrict__ W1,
                      const float* __restrict__ W2, const float* __restrict__ W3,
                      const float* __restrict__ b0, const float* __restrict__ b1,
                      const float* __restrict__ b2, const float* __restrict__ b3,
                      float* __restrict__ C, int M) {
    __shared__ __half sA[2][BM * ASTR];
    __shared__ __half sB[2][BK * BSTR];

    const int which = blockIdx.x >> 1;
    const float* B    = (which == 0) ? W0 : (which == 1) ? W1 : (which == 2) ? W2 : W3;
    const float* bias = (which == 0) ? b0 : (which == 1) ? b1 : (which == 2) ? b2 : b3;

    const int tid  = threadIdx.x;
    const int lane = tid & 31;
    const int wid  = tid >> 5;
    const int wm   = (wid & 3) * 32;
    const int wn   = (wid >> 2) * 64;
    const int brow = blockIdx.y * BM;
    const int bcol = (blockIdx.x & 1) * BN;

    float c[2][8][4];
    #pragma unroll
    for (int i = 0; i < 2; i++)
        #pragma unroll
        for (int j = 0; j < 8; j++)
            #pragma unroll
            for (int r = 0; r < 4; r++) c[i][j][r] = 0.f;

    // global load mapping: per thread 2 float4 of A (128x16) and 2 of B (16x128)
    int arow[2], akf[2], bkr[2], bnf[2];
    const float* aptr[2];
    const float* bptr0[2];
    #pragma unroll
    for (int i = 0; i < 2; i++) {
        int idx = tid + i * 256;
        arow[i] = idx >> 2;  akf[i] = (idx & 3) * 4;
        bkr[i]  = idx >> 5;  bnf[i] = (idx & 31) * 4;
        int gr = brow + arow[i];
        if (gr >= M) gr = M - 1;
        aptr[i]  = A + (size_t)gr * 256 + akf[i];
        bptr0[i] = B + (size_t)bkr[i] * 256 + bcol + bnf[i];
    }

    // preload tile 0 into buffer 0
    #pragma unroll
    for (int i = 0; i < 2; i++) {
        *(uint2*)&sA[0][arow[i] * ASTR + akf[i]] = pack4h(*(const float4*)aptr[i]);
        *(uint2*)&sB[0][bkr[i] * BSTR + bnf[i]]  = pack4h(*(const float4*)bptr0[i]);
    }
    __syncthreads();

    // ldmatrix lane addressing (constant per thread)
    const int lrow = lane & 15;           // row within 16-row block
    const int lhi  = (lane >> 4) * 8;     // second-half offset (k for A, n for B)

    const int NSTEP = 256 / BK;   // 16
    float4 pa[2], pb[2];

    for (int t = 0; t < NSTEP; t++) {
        const int cur = t & 1;
        const bool has_next = (t + 1 < NSTEP);
        if (has_next) {
            int k0 = (t + 1) * BK;
            #pragma unroll
            for (int i = 0; i < 2; i++) {
                pa[i] = *(const float4*)(aptr[i] + k0);
                pb[i] = *(const float4*)(bptr0[i] + (size_t)k0 * 256);
            }
        }

        uint32_t abase = (uint32_t)__cvta_generic_to_shared(&sA[cur][0]);
        uint32_t bbase = (uint32_t)__cvta_generic_to_shared(&sB[cur][0]);

        // A fragments: mt in {0,1}, x4 ldmatrix over (m16 x k16)
        uint32_t af[2][4];
        #pragma unroll
        for (int mt = 0; mt < 2; mt++) {
            uint32_t addr = abase + ((wm + mt * 16 + lrow) * ASTR + lhi) * 2;
            asm volatile("ldmatrix.sync.aligned.m8n8.x4.shared.b16 {%0,%1,%2,%3}, [%4];"
                         : "=r"(af[mt][0]), "=r"(af[mt][1]),
                           "=r"(af[mt][2]), "=r"(af[mt][3])
                         : "r"(addr));
        }
        // B fragments: 8 n-tiles; each x4.trans covers 2 n-tiles x full k16
        uint32_t bf[8][2];
        #pragma unroll
        for (int nt2 = 0; nt2 < 4; nt2++) {
            uint32_t addr = bbase + (lrow * BSTR + wn + nt2 * 16 + lhi) * 2;
            asm volatile("ldmatrix.sync.aligned.m8n8.x4.trans.shared.b16 {%0,%1,%2,%3}, [%4];"
                         : "=r"(bf[2 * nt2][0]), "=r"(bf[2 * nt2][1]),
                           "=r"(bf[2 * nt2 + 1][0]), "=r"(bf[2 * nt2 + 1][1])
                         : "r"(addr));
        }

        #pragma unroll
        for (int mt = 0; mt < 2; mt++)
            #pragma unroll
            for (int nt = 0; nt < 8; nt++) {
                asm volatile(
                    "mma.sync.aligned.m16n8k16.row.col.f32.f16.f16.f32 "
                    "{%0,%1,%2,%3}, {%4,%5,%6,%7}, {%8,%9}, {%0,%1,%2,%3};"
                    : "+f"(c[mt][nt][0]), "+f"(c[mt][nt][1]),
                      "+f"(c[mt][nt][2]), "+f"(c[mt][nt][3])
                    : "r"(af[mt][0]), "r"(af[mt][1]),
                      "r"(af[mt][2]), "r"(af[mt][3]),
                      "r"(bf[nt][0]), "r"(bf[nt][1]));
            }

        if (has_next) {
            const int nxt = cur ^ 1;
            #pragma unroll
            for (int i = 0; i < 2; i++) {
                *(uint2*)&sA[nxt][arow[i] * ASTR + akf[i]] = pack4h(pa[i]);
                *(uint2*)&sB[nxt][bkr[i] * BSTR + bnf[i]]  = pack4h(pb[i]);
            }
        }
        __syncthreads();
    }

    // epilogue: C[row*1024 + which*256 + col] = acc + bias
    const int l4 = lane & 3, l8 = lane >> 2;
    float* Cb = C + (size_t)which * 256;
    #pragma unroll
    for (int mt = 0; mt < 2; mt++) {
        #pragma unroll
        for (int half = 0; half < 2; half++) {
            int grow = brow + wm + mt * 16 + l8 + half * 8;
            if (grow < M) {
                #pragma unroll
                for (int nt = 0; nt < 8; nt++) {
                    int gcol = bcol + wn + nt * 8 + 2 * l4;
                    float2 o;
                    o.x = c[mt][nt][half * 2 + 0] + bias[gcol + 0];
                    o.y = c[mt][nt][half * 2 + 1] + bias[gcol + 1];
                    *(float2*)(Cb + (size_t)grow * 1024 + gcol) = o;
                }
            }
        }
    }
}

// ---------------- edge attention: one warp per node, plain-exp softmax -------
__global__ void edge_attn_kernel(const float* __restrict__ qkvs,
                                 float* __restrict__ out) {
    int warp = (blockIdx.x * blockDim.x + threadIdx.x) >> 5;
    if (warp >= NN) return;
    int lane = threadIdx.x & 31;
    const int ch = lane * 8;
    const float* nb = qkvs + (size_t)warp * 1024;

    float4 q0 = *(const float4*)(nb + ch);
    float4 q1 = *(const float4*)(nb + ch + 4);

    float d = 0.f;
    float acc[8];
    #pragma unroll
    for (int i = 0; i < 8; i++) acc[i] = 0.f;

    const int e0 = g_rowptr[warp], e1 = g_rowptr[warp + 1];
    int e = e0;

    for (; e + 3 < e1; e += 4) {
        int s0 = g_col[e], s1 = g_col[e + 1], s2 = g_col[e + 2], s3 = g_col[e + 3];
        const float* kp0 = qkvs + (size_t)s0 * 1024 + 256 + ch;
        const float* kp1 = qkvs + (size_t)s1 * 1024 + 256 + ch;
        const float* kp2 = qkvs + (size_t)s2 * 1024 + 256 + ch;
        const float* kp3 = qkvs + (size_t)s3 * 1024 + 256 + ch;
        float4 ka0 = *(const float4*)kp0, ka1 = *(const float4*)(kp0 + 4);
        float4 kb0 = *(const float4*)kp1, kb1 = *(const float4*)(kp1 + 4);
        float4 kc0 = *(const float4*)kp2, kc1 = *(const float4*)(kp2 + 4);
        float4 kd0 = *(const float4*)kp3, kd1 = *(const float4*)(kp3 + 4);
        float4 va0 = *(const float4*)(kp0 + 256), va1 = *(const float4*)(kp0 + 260);
        float4 vb0 = *(const float4*)(kp1 + 256), vb1 = *(const float4*)(kp1 + 260);
        float4 vc0 = *(const float4*)(kp2 + 256), vc1 = *(const float4*)(kp2 + 260);
        float4 vd0 = *(const float4*)(kp3 + 256), vd1 = *(const float4*)(kp3 + 260);

        float p0 = q0.x*ka0.x + q0.y*ka0.y + q0.z*ka0.z + q0.w*ka0.w
                 + q1.x*ka1.x + q1.y*ka1.y + q1.z*ka1.z + q1.w*ka1.w;
        float p1 = q0.x*kb0.x + q0.y*kb0.y + q0.z*kb0.z + q0.w*kb0.w
                 + q1.x*kb1.x + q1.y*kb1.y + q1.z*kb1.z + q1.w*kb1.w;
        float p2 = q0.x*kc0.x + q0.y*kc0.y + q0.z*kc0.z + q0.w*kc0.w
                 + q1.x*kc1.x + q1.y*kc1.y + q1.z*kc1.z + q1.w*kc1.w;
        float p3 = q0.x*kd0.x + q0.y*kd0.y + q0.z*kd0.z + q0.w*kd0.w
                 + q1.x*kd1.x + q1.y*kd1.y + q1.z*kd1.z + q1.w*kd1.w;
        p0 += __shfl_xor_sync(0xffffffff, p0, 1);
        p1 += __shfl_xor_sync(0xffffffff, p1, 1);
        p2 += __shfl_xor_sync(0xffffffff, p2, 1);
        p3 += __shfl_xor_sync(0xffffffff, p3, 1);
        p0 += __shfl_xor_sync(0xffffffff, p0, 2);
        p1 += __shfl_xor_sync(0xffffffff, p1, 2);
        p2 += __shfl_xor_sync(0xffffffff, p2, 2);
        p3 += __shfl_xor_sync(0xffffffff, p3, 2);
        p0 += __shfl_xor_sync(0xffffffff, p0, 4);
        p1 += __shfl_xor_sync(0xffffffff, p1, 4);
        p2 += __shfl_xor_sync(0xffffffff, p2, 4);
        p3 += __shfl_xor_sync(0xffffffff, p3, 4);

        float pe0 = __expf(fminf(p0 * SCALE, 85.f));
        float pe1 = __expf(fminf(p1 * SCALE, 85.f));
        float pe2 = __expf(fminf(p2 * SCALE, 85.f));
        float pe3 = __expf(fminf(p3 * SCALE, 85.f));
        d += pe0 + pe1 + pe2 + pe3;
        acc[0] += pe0*va0.x + pe1*vb0.x + pe2*vc0.x + pe3*vd0.x;
        acc[1] += pe0*va0.y + pe1*vb0.y + pe2*vc0.y + pe3*vd0.y;
        acc[2] += pe0*va0.z + pe1*vb0.z + pe2*vc0.z + pe3*vd0.z;
        acc[3] += pe0*va0.w + pe1*vb0.w + pe2*vc0.w + pe3*vd0.w;
        acc[4] += pe0*va1.x + pe1*vb1.x + pe2*vc1.x + pe3*vd1.x;
        acc[5] += pe0*va1.y + pe1*vb1.y + pe2*vc1.y + pe3*vd1.y;
        acc[6] += pe0*va1.z + pe1*vb1.z + pe2*vc1.z + pe3*vd1.z;
        acc[7] += pe0*va1.w + pe1*vb1.w + pe2*vc1.w + pe3*vd1.w;
    }

    for (; e < e1; e++) {
        int s0 = g_col[e];
        const float* kp = qkvs + (size_t)s0 * 1024 + 256 + ch;
        float4 ka0 = *(const float4*)kp, ka1 = *(const float4*)(kp + 4);
        float4 va0 = *(const float4*)(kp + 256), va1 = *(const float4*)(kp + 260);
        float p = q0.x*ka0.x + q0.y*ka0.y + q0.z*ka0.z + q0.w*ka0.w
                + q1.x*ka1.x + q1.y*ka1.y + q1.z*ka1.z + q1.w*ka1.w;
        p += __shfl_xor_sync(0xffffffff, p, 1);
        p += __shfl_xor_sync(0xffffffff, p, 2);
        p += __shfl_xor_sync(0xffffffff, p, 4);
        float pe = __expf(fminf(p * SCALE, 85.f));
        d += pe;
        acc[0] += pe * va0.x;
        acc[1] += pe * va0.y;
        acc[2] += pe * va0.z;
        acc[3] += pe * va0.w;
        acc[4] += pe * va1.x;
        acc[5] += pe * va1.y;
        acc[6] += pe * va1.z;
        acc[7] += pe * va1.w;
    }

    float inv = (d > 0.f) ? 1.f / d : 0.f;
    const float* sp = nb + 768 + ch;
    float4 s0v = *(const float4*)sp;
    float4 s1v = *(const float4*)(sp + 4);
    float4 o0, o1;
    o0.x = fmaxf(acc[0] * inv + s0v.x, 0.f);
    o0.y = fmaxf(acc[1] * inv + s0v.y, 0.f);
    o0.z = fmaxf(acc[2] * inv + s0v.z, 0.f);
    o0.w = fmaxf(acc[3] * inv + s0v.w, 0.f);
    o1.x = fmaxf(acc[4] * inv + s1v.x, 0.f);
    o1.y = fmaxf(acc[5] * inv + s1v.y, 0.f);
    o1.z = fmaxf(acc[6] * inv + s1v.z, 0.f);
    o1.w = fmaxf(acc[7] * inv + s1v.w, 0.f);
    float* op = out + (size_t)warp * 256 + ch;
    *(float4*)op       = o0;
    *(float4*)(op + 4) = o1;
}

// ---------------- launch ------------------------------------------------------
extern "C" void kernel_launch(void* const* d_in, const int* in_sizes, int n_in,
                              void* d_out, int out_size) {
    const float* x   = (const float*)d_in[0];
    const int*   ei  = (const int*)d_in[1];
    const float* Wq  = (const float*)d_in[2];
    const float* bq  = (const float*)d_in[3];
    const float* Wk  = (const float*)d_in[4];
    const float* bk  = (const float*)d_in[5];
    const float* Wv  = (const float*)d_in[6];
    const float* bv  = (const float*)d_in[7];
    const float* Ws  = (const float*)d_in[8];
    const float* bs  = (const float*)d_in[9];
    float* out = (float*)d_out;

    float *qkvs, *hA, *hB;
    cudaGetSymbolAddress((void**)&qkvs, g_qkvs);
    cudaGetSymbolAddress((void**)&hA,   g_hA);
    cudaGetSymbolAddress((void**)&hB,   g_hB);

    zero_counts_kernel<<<(NN + 255) / 256, 256>>>();
    count_dst_kernel<<<(EE + 255) / 256, 256>>>(ei);
    exscan_kernel<<<1, 1024>>>();
    fill_csr_kernel<<<(EE + 255) / 256, 256>>>(ei);

    dim3 gemm_grid(8, (NN + BM - 1) / BM);
    int edge_blocks = (NN + 7) / 8;

    const float* hin = x;
    for (int l = 0; l < LL; l++) {
        size_t wo = (size_t)l * DD * HC;
        gemm_qkvs_kernel<<<gemm_grid, 256>>>(
            hin,
            Wq + wo, Wk + wo, Wv + wo, Ws + wo,
            bq + l * HC, bk + l * HC, bv + l * HC, bs + l * HC,
            qkvs, NN);

        float* hout = (l == LL - 1) ? out : ((l == 0) ? hA : hB);
        edge_attn_kernel<<<edge_blocks, 256>>>(qkvs, hout);
        hin = hout;
    }
}

// round 6
// speedup vs baseline: 1.5833x; 1.2644x over previous
#include <cuda_runtime.h>
#include <cuda_fp16.h>
#include <math.h>
#include <stdint.h>

#define NN 50000
#define EE 800000
#define DD 256
#define HC 256          // H*C = 4*64
#define LL 3
#define SCALE 0.125f    // 1/sqrt(64)

// ---------------- scratch (static device globals; no allocation) -------------
__device__ float  g_qs[NN * 512];    // per node: [q(256) | s(256)] fp32
__device__ __half g_kv[NN * 512];    // per node: [k(256) | v(256)] fp16
__device__ float  g_hA[NN * HC];
__device__ float  g_hB[NN * HC];
__device__ int    g_rowptr[NN + 1];
__device__ int    g_cnt[NN];
__device__ int    g_offs[NN];
__device__ int    g_col[EE];

// ---------------- CSR construction ------------------------------------------
__global__ void zero_counts_kernel() {
    int i = blockIdx.x * blockDim.x + threadIdx.x;
    if (i < NN) { g_cnt[i] = 0; g_offs[i] = 0; }
}

__global__ void count_dst_kernel(const int* __restrict__ edge_index) {
    int e = blockIdx.x * blockDim.x + threadIdx.x;
    if (e < EE) {
        int d = edge_index[EE + e];
        atomicAdd(&g_cnt[d], 1);
    }
}

__global__ void exscan_kernel() {
    __shared__ int warpsum[32];
    __shared__ int carry_s;
    int tid = threadIdx.x, lane = tid & 31, wid = tid >> 5;
    if (tid == 0) carry_s = 0;
    __syncthreads();
    for (int base = 0; base < NN; base += 1024) {
        int i = base + tid;
        int val = (i < NN) ? g_cnt[i] : 0;
        int x = val;
        #pragma unroll
        for (int off = 1; off < 32; off <<= 1) {
            int y = __shfl_up_sync(0xffffffff, x, off);
            if (lane >= off) x += y;
        }
        if (lane == 31) warpsum[wid] = x;
        __syncthreads();
        if (wid == 0) {
            int w = warpsum[lane];
            #pragma unroll
            for (int off = 1; off < 32; off <<= 1) {
                int y = __shfl_up_sync(0xffffffff, w, off);
                if (lane >= off) w += y;
            }
            warpsum[lane] = w;
        }
        __syncthreads();
        int incl = x + (wid > 0 ? warpsum[wid - 1] : 0);
        int c = carry_s;
        if (i < NN) g_rowptr[i] = c + incl - val;
        __syncthreads();
        if (tid == 1023) carry_s = c + incl;
        __syncthreads();
    }
    if (tid == 0) g_rowptr[NN] = carry_s;
}

__global__ void fill_csr_kernel(const int* __restrict__ edge_index) {
    int e = blockIdx.x * blockDim.x + threadIdx.x;
    if (e < EE) {
        int s = edge_index[e];
        int d = edge_index[EE + e];
        int pos = g_rowptr[d] + atomicAdd(&g_offs[d], 1);
        g_col[pos] = s;
    }
}

// ---------------- fused FP16 GEMM -------------------------------------------
// which 0: q -> g_qs[..,0:256] fp32     which 1: k -> g_kv[..,0:256] fp16
// which 2: v -> g_kv[..,256:512] fp16   which 3: s -> g_qs[..,256:512] fp32
#define BM 128
#define BN 128
#define BK 16
#define ASTR 24
#define BSTR 136

__device__ __forceinline__ uint2 pack4h(float4 v) {
    __half2 a = __floats2half2_rn(v.x, v.y);
    __half2 b = __floats2half2_rn(v.z, v.w);
    uint2 r;
    r.x = *(uint32_t*)&a;
    r.y = *(uint32_t*)&b;
    return r;
}

__global__ __launch_bounds__(256, 2)
void gemm_qkvs_kernel(const float* __restrict__ A,
                      const float* __restrict__ W0, const float* __restrict__ W1,
                      const float* __restrict__ W2, const float* __restrict__ W3,
                      const float* __restrict__ b0, const float* __restrict__ b1,
                      const float* __restrict__ b2, const float* __restrict__ b3,
                      float* __restrict__ qs, __half* __restrict__ kv, int M) {
    __shared__ __half sA[2][BM * ASTR];
    __shared__ __half sB[2][BK * BSTR];

    const int which = blockIdx.x >> 1;
    const float* B    = (which == 0) ? W0 : (which == 1) ? W1 : (which == 2) ? W2 : W3;
    const float* bias = (which == 0) ? b0 : (which == 1) ? b1 : (which == 2) ? b2 : b3;

    const int tid  = threadIdx.x;
    const int lane = tid & 31;
    const int wid  = tid >> 5;
    const int wm   = (wid & 3) * 32;
    const int wn   = (wid >> 2) * 64;
    const int brow = blockIdx.y * BM;
    const int bcol = (blockIdx.x & 1) * BN;

    float c[2][8][4];
    #pragma unroll
    for (int i = 0; i < 2; i++)
        #pragma unroll
        for (int j = 0; j < 8; j++)
            #pragma unroll
            for (int r = 0; r < 4; r++) c[i][j][r] = 0.f;

    int arow[2], akf[2], bkr[2], bnf[2];
    const float* aptr[2];
    const float* bptr0[2];
    #pragma unroll
    for (int i = 0; i < 2; i++) {
        int idx = tid + i * 256;
        arow[i] = idx >> 2;  akf[i] = (idx & 3) * 4;
        bkr[i]  = idx >> 5;  bnf[i] = (idx & 31) * 4;
        int gr = brow + arow[i];
        if (gr >= M) gr = M - 1;
        aptr[i]  = A + (size_t)gr * 256 + akf[i];
        bptr0[i] = B + (size_t)bkr[i] * 256 + bcol + bnf[i];
    }

    #pragma unroll
    for (int i = 0; i < 2; i++) {
        *(uint2*)&sA[0][arow[i] * ASTR + akf[i]] = pack4h(*(const float4*)aptr[i]);
        *(uint2*)&sB[0][bkr[i] * BSTR + bnf[i]]  = pack4h(*(const float4*)bptr0[i]);
    }
    __syncthreads();

    const int lrow = lane & 15;
    const int lhi  = (lane >> 4) * 8;

    const int NSTEP = 256 / BK;   // 16
    float4 pa[2], pb[2];

    for (int t = 0; t < NSTEP; t++) {
        const int cur = t & 1;
        const bool has_next = (t + 1 < NSTEP);
        if (has_next) {
            int k0 = (t + 1) * BK;
            #pragma unroll
            for (int i = 0; i < 2; i++) {
                pa[i] = *(const float4*)(aptr[i] + k0);
                pb[i] = *(const float4*)(bptr0[i] + (size_t)k0 * 256);
            }
        }

        uint32_t abase = (uint32_t)__cvta_generic_to_shared(&sA[cur][0]);
        uint32_t bbase = (uint32_t)__cvta_generic_to_shared(&sB[cur][0]);

        uint32_t af[2][4];
        #pragma unroll
        for (int mt = 0; mt < 2; mt++) {
            uint32_t addr = abase + ((wm + mt * 16 + lrow) * ASTR + lhi) * 2;
            asm volatile("ldmatrix.sync.aligned.m8n8.x4.shared.b16 {%0,%1,%2,%3}, [%4];"
                         : "=r"(af[mt][0]), "=r"(af[mt][1]),
                           "=r"(af[mt][2]), "=r"(af[mt][3])
                         : "r"(addr));
        }
        uint32_t bf[8][2];
        #pragma unroll
        for (int nt2 = 0; nt2 < 4; nt2++) {
            uint32_t addr = bbase + (lrow * BSTR + wn + nt2 * 16 + lhi) * 2;
            asm volatile("ldmatrix.sync.aligned.m8n8.x4.trans.shared.b16 {%0,%1,%2,%3}, [%4];"
                         : "=r"(bf[2 * nt2][0]), "=r"(bf[2 * nt2][1]),
                           "=r"(bf[2 * nt2 + 1][0]), "=r"(bf[2 * nt2 + 1][1])
                         : "r"(addr));
        }

        #pragma unroll
        for (int mt = 0; mt < 2; mt++)
            #pragma unroll
            for (int nt = 0; nt < 8; nt++) {
                asm volatile(
                    "mma.sync.aligned.m16n8k16.row.col.f32.f16.f16.f32 "
                    "{%0,%1,%2,%3}, {%4,%5,%6,%7}, {%8,%9}, {%0,%1,%2,%3};"
                    : "+f"(c[mt][nt][0]), "+f"(c[mt][nt][1]),
                      "+f"(c[mt][nt][2]), "+f"(c[mt][nt][3])
                    : "r"(af[mt][0]), "r"(af[mt][1]),
                      "r"(af[mt][2]), "r"(af[mt][3]),
                      "r"(bf[nt][0]), "r"(bf[nt][1]));
            }

        if (has_next) {
            const int nxt = cur ^ 1;
            #pragma unroll
            for (int i = 0; i < 2; i++) {
                *(uint2*)&sA[nxt][arow[i] * ASTR + akf[i]] = pack4h(pa[i]);
                *(uint2*)&sB[nxt][bkr[i] * BSTR + bnf[i]]  = pack4h(pb[i]);
            }
        }
        __syncthreads();
    }

    // epilogue
    const int l4 = lane & 3, l8 = lane >> 2;
    const bool is_f32 = (which == 0) || (which == 3);
    float*  Cf = qs + ((which == 3) ? 256 : 0);
    __half* Ch = kv + ((which == 2) ? 256 : 0);
    #pragma unroll
    for (int mt = 0; mt < 2; mt++) {
        #pragma unroll
        for (int half = 0; half < 2; half++) {
            int grow = brow + wm + mt * 16 + l8 + half * 8;
            if (grow < M) {
                #pragma unroll
                for (int nt = 0; nt < 8; nt++) {
                    int gcol = bcol + wn + nt * 8 + 2 * l4;
                    float ox = c[mt][nt][half * 2 + 0] + bias[gcol + 0];
                    float oy = c[mt][nt][half * 2 + 1] + bias[gcol + 1];
                    if (is_f32) {
                        float2 o = make_float2(ox, oy);
                        *(float2*)(Cf + (size_t)grow * 512 + gcol) = o;
                    } else {
                        __half2 o = __floats2half2_rn(ox, oy);
                        *(__half2*)(Ch + (size_t)grow * 512 + gcol) = o;
                    }
                }
            }
        }
    }
}

// ---------------- edge attention: fp16 k/v gather, plain-exp softmax ---------
// per edge per lane: one uint4 (8 half k) + one uint4 (8 half v) = 32B;
// per edge warp-wide: 1KB (was 2KB in fp32).
__global__ void edge_attn_kernel(const float* __restrict__ qs,
                                 const __half* __restrict__ kv,
                                 float* __restrict__ out) {
    int warp = (blockIdx.x * blockDim.x + threadIdx.x) >> 5;
    if (warp >= NN) return;
    int lane = threadIdx.x & 31;
    const int ch = lane * 8;
    const float* nb = qs + (size_t)warp * 512;

    float4 q0 = *(const float4*)(nb + ch);
    float4 q1 = *(const float4*)(nb + ch + 4);

    float d = 0.f;
    float acc[8];
    #pragma unroll
    for (int i = 0; i < 8; i++) acc[i] = 0.f;

    const int e0 = g_rowptr[warp], e1 = g_rowptr[warp + 1];
    int e = e0;

    #define LOADKV(S, KK, VV)                                                  \
        {                                                                      \
            const __half* p_ = kv + (size_t)(S) * 512 + ch;                    \
            KK = *(const uint4*)p_;                                            \
            VV = *(const uint4*)(p_ + 256);                                    \
        }
    #define DOT8(KK, P)                                                        \
        {                                                                      \
            float2 h0_ = __half22float2(*(__half2*)&KK.x);                     \
            float2 h1_ = __half22float2(*(__half2*)&KK.y);                     \
            float2 h2_ = __half22float2(*(__half2*)&KK.z);                     \
            float2 h3_ = __half22float2(*(__half2*)&KK.w);                     \
            P = q0.x*h0_.x + q0.y*h0_.y + q0.z*h1_.x + q0.w*h1_.y              \
              + q1.x*h2_.x + q1.y*h2_.y + q1.z*h3_.x + q1.w*h3_.y;             \
        }
    #define ACCV(VV, PE)                                                       \
        {                                                                      \
            float2 h0_ = __half22float2(*(__half2*)&VV.x);                     \
            float2 h1_ = __half22float2(*(__half2*)&VV.y);                     \
            float2 h2_ = __half22float2(*(__half2*)&VV.z);                     \
            float2 h3_ = __half22float2(*(__half2*)&VV.w);                     \
            acc[0] += PE * h0_.x; acc[1] += PE * h0_.y;                        \
            acc[2] += PE * h1_.x; acc[3] += PE * h1_.y;                        \
            acc[4] += PE * h2_.x; acc[5] += PE * h2_.y;                        \
            acc[6] += PE * h3_.x; acc[7] += PE * h3_.y;                        \
        }

    for (; e + 3 < e1; e += 4) {
        int s0 = g_col[e], s1 = g_col[e + 1], s2 = g_col[e + 2], s3 = g_col[e + 3];
        uint4 k0v, k1v, k2v, k3v, v0v, v1v, v2v, v3v;
        LOADKV(s0, k0v, v0v);
        LOADKV(s1, k1v, v1v);
        LOADKV(s2, k2v, v2v);
        LOADKV(s3, k3v, v3v);

        float p0, p1, p2, p3;
        DOT8(k0v, p0);
        DOT8(k1v, p1);
        DOT8(k2v, p2);
        DOT8(k3v, p3);
        p0 += __shfl_xor_sync(0xffffffff, p0, 1);
        p1 += __shfl_xor_sync(0xffffffff, p1, 1);
        p2 += __shfl_xor_sync(0xffffffff, p2, 1);
        p3 += __shfl_xor_sync(0xffffffff, p3, 1);
        p0 += __shfl_xor_sync(0xffffffff, p0, 2);
        p1 += __shfl_xor_sync(0xffffffff, p1, 2);
        p2 += __shfl_xor_sync(0xffffffff, p2, 2);
        p3 += __shfl_xor_sync(0xffffffff, p3, 2);
        p0 += __shfl_xor_sync(0xffffffff, p0, 4);
        p1 += __shfl_xor_sync(0xffffffff, p1, 4);
        p2 += __shfl_xor_sync(0xffffffff, p2, 4);
        p3 += __shfl_xor_sync(0xffffffff, p3, 4);

        float pe0 = __expf(fminf(p0 * SCALE, 85.f));
        float pe1 = __expf(fminf(p1 * SCALE, 85.f));
        float pe2 = __expf(fminf(p2 * SCALE, 85.f));
        float pe3 = __expf(fminf(p3 * SCALE, 85.f));
        d += pe0 + pe1 + pe2 + pe3;
        ACCV(v0v, pe0);
        ACCV(v1v, pe1);
        ACCV(v2v, pe2);
        ACCV(v3v, pe3);
    }

    for (; e < e1; e++) {
        int s0 = g_col[e];
        uint4 kk, vv;
        LOADKV(s0, kk, vv);
        float p;
        DOT8(kk, p);
        p += __shfl_xor_sync(0xffffffff, p, 1);
        p += __shfl_xor_sync(0xffffffff, p, 2);
        p += __shfl_xor_sync(0xffffffff, p, 4);
        float pe = __expf(fminf(p * SCALE, 85.f));
        d += pe;
        ACCV(vv, pe);
    }

    float inv = (d > 0.f) ? 1.f / d : 0.f;
    const float* sp = nb + 256 + ch;
    float4 s0v = *(const float4*)sp;
    float4 s1v = *(const float4*)(sp + 4);
    float4 o0, o1;
    o0.x = fmaxf(acc[0] * inv + s0v.x, 0.f);
    o0.y = fmaxf(acc[1] * inv + s0v.y, 0.f);
    o0.z = fmaxf(acc[2] * inv + s0v.z, 0.f);
    o0.w = fmaxf(acc[3] * inv + s0v.w, 0.f);
    o1.x = fmaxf(acc[4] * inv + s1v.x, 0.f);
    o1.y = fmaxf(acc[5] * inv + s1v.y, 0.f);
    o1.z = fmaxf(acc[6] * inv + s1v.z, 0.f);
    o1.w = fmaxf(acc[7] * inv + s1v.w, 0.f);
    float* op = out + (size_t)warp * 256 + ch;
    *(float4*)op       = o0;
    *(float4*)(op + 4) = o1;
}

// ---------------- launch ------------------------------------------------------
extern "C" void kernel_launch(void* const* d_in, const int* in_sizes, int n_in,
                              void* d_out, int out_size) {
    const float* x   = (const float*)d_in[0];
    const int*   ei  = (const int*)d_in[1];
    const float* Wq  = (const float*)d_in[2];
    const float* bq  = (const float*)d_in[3];
    const float* Wk  = (const float*)d_in[4];
    const float* bk  = (const float*)d_in[5];
    const float* Wv  = (const float*)d_in[6];
    const float* bv  = (const float*)d_in[7];
    const float* Ws  = (const float*)d_in[8];
    const float* bs  = (const float*)d_in[9];
    float* out = (float*)d_out;

    float  *qs, *hA, *hB;
    __half *kvp;
    cudaGetSymbolAddress((void**)&qs,  g_qs);
    cudaGetSymbolAddress((void**)&kvp, g_kv);
    cudaGetSymbolAddress((void**)&hA,  g_hA);
    cudaGetSymbolAddress((void**)&hB,  g_hB);

    zero_counts_kernel<<<(NN + 255) / 256, 256>>>();
    count_dst_kernel<<<(EE + 255) / 256, 256>>>(ei);
    exscan_kernel<<<1, 1024>>>();
    fill_csr_kernel<<<(EE + 255) / 256, 256>>>(ei);

    dim3 gemm_grid(8, (NN + BM - 1) / BM);
    int edge_blocks = (NN + 7) / 8;

    const float* hin = x;
    for (int l = 0; l < LL; l++) {
        size_t wo = (size_t)l * DD * HC;
        gemm_qkvs_kernel<<<gemm_grid, 256>>>(
            hin,
            Wq + wo, Wk + wo, Wv + wo, Ws + wo,
            bq + l * HC, bk + l * HC, bv + l * HC, bs + l * HC,
            qs, kvp, NN);

        float* hout = (l == LL - 1) ? out : ((l == 0) ? hA : hB);
        edge_attn_kernel<<<edge_blocks, 256>>>(qs, kvp, hout);
        hin = hout;
    }
}

// round 7
// speedup vs baseline: 1.7395x; 1.0987x over previous
#include <cuda_runtime.h>
#include <cuda_fp16.h>
#include <math.h>
#include <stdint.h>

#define NN 50000
#define EE 800000
#define DD 256
#define HC 256
#define LL 3
#define SCALE 0.125f

// ---------------- scratch ----------------------------------------------------
__device__ float  g_qs[NN * 512];          // [q(256) | s(256)] fp32
__device__ __half g_kv[NN * 512];          // [k(256) | v(256)] fp16
__device__ __half g_Ah[NN * 256];          // current layer input features fp16
__device__ __half g_Wh[LL * 4 * 256 * 256];// fp16 weights [l][q,k,v,s][k][n]
__device__ int    g_rowptr[NN + 1];
__device__ int    g_cnt[NN];
__device__ int    g_offs[NN];
__device__ int    g_col[EE];

// ---------------- converts ----------------------------------------------------
__global__ void convert_w_kernel(const float* __restrict__ Wq, const float* __restrict__ Wk,
                                 const float* __restrict__ Wv, const float* __restrict__ Ws,
                                 __half* __restrict__ Wh) {
    int idx = blockIdx.x * blockDim.x + threadIdx.x;   // over LL*4*65536
    if (idx < LL * 4 * 65536) {
        int l = idx >> 18;
        int w = (idx >> 16) & 3;
        int off = idx & 65535;
        const float* src = (w == 0) ? Wq : (w == 1) ? Wk : (w == 2) ? Wv : Ws;
        Wh[idx] = __float2half(src[l * 65536 + off]);
    }
}

__global__ void convert_x_kernel(const float* __restrict__ x, __half* __restrict__ Ah) {
    int idx = blockIdx.x * blockDim.x + threadIdx.x;
    if (idx < NN * 256) Ah[idx] = __float2half(x[idx]);
}

// ---------------- CSR construction ------------------------------------------
__global__ void zero_counts_kernel() {
    int i = blockIdx.x * blockDim.x + threadIdx.x;
    if (i < NN) { g_cnt[i] = 0; g_offs[i] = 0; }
}

__global__ void count_dst_kernel(const int* __restrict__ edge_index) {
    int e = blockIdx.x * blockDim.x + threadIdx.x;
    if (e < EE) atomicAdd(&g_cnt[edge_index[EE + e]], 1);
}

__global__ void exscan_kernel() {
    __shared__ int warpsum[32];
    __shared__ int carry_s;
    int tid = threadIdx.x, lane = tid & 31, wid = tid >> 5;
    if (tid == 0) carry_s = 0;
    __syncthreads();
    for (int base = 0; base < NN; base += 1024) {
        int i = base + tid;
        int val = (i < NN) ? g_cnt[i] : 0;
        int x = val;
        #pragma unroll
        for (int off = 1; off < 32; off <<= 1) {
            int y = __shfl_up_sync(0xffffffff, x, off);
            if (lane >= off) x += y;
        }
        if (lane == 31) warpsum[wid] = x;
        __syncthreads();
        if (wid == 0) {
            int w = warpsum[lane];
            #pragma unroll
            for (int off = 1; off < 32; off <<= 1) {
                int y = __shfl_up_sync(0xffffffff, w, off);
                if (lane >= off) w += y;
            }
            warpsum[lane] = w;
        }
        __syncthreads();
        int incl = x + (wid > 0 ? warpsum[wid - 1] : 0);
        int c = carry_s;
        if (i < NN) g_rowptr[i] = c + incl - val;
        __syncthreads();
        if (tid == 1023) carry_s = c + incl;
        __syncthreads();
    }
    if (tid == 0) g_rowptr[NN] = carry_s;
}

__global__ void fill_csr_kernel(const int* __restrict__ edge_index) {
    int e = blockIdx.x * blockDim.x + threadIdx.x;
    if (e < EE) {
        int s = edge_index[e];
        int d = edge_index[EE + e];
        int pos = g_rowptr[d] + atomicAdd(&g_offs[d], 1);
        g_col[pos] = s;
    }
}

// ---------------- FP16 GEMM via cp.async, BK=32 ------------------------------
#define BM 128
#define BN 128
#define BK 32
#define ASTR 40     // halfs per A row (32+8): r*20%32 distinct over 8 rows
#define BSTR 136    // halfs per B row (128+8): k*4%32 distinct over 8 rows

__device__ __forceinline__ void cp_async16(uint32_t dst, const void* src) {
    asm volatile("cp.async.cg.shared.global [%0], [%1], 16;" :: "r"(dst), "l"(src));
}

__global__ __launch_bounds__(256, 2)
void gemm_qkvs_kernel(const __half* __restrict__ Ah,
                      const __half* __restrict__ Wl,   // this layer: 4 x [256][256] fp16
                      const float* __restrict__ b0, const float* __restrict__ b1,
                      const float* __restrict__ b2, const float* __restrict__ b3,
                      float* __restrict__ qs, __half* __restrict__ kv, int M) {
    __shared__ __half sA[2][BM * ASTR];
    __shared__ __half sB[2][BK * BSTR];

    const int which = blockIdx.x >> 1;
    const __half* B   = Wl + which * 65536;
    const float* bias = (which == 0) ? b0 : (which == 1) ? b1 : (which == 2) ? b2 : b3;

    const int tid  = threadIdx.x;
    const int lane = tid & 31;
    const int wid  = tid >> 5;
    const int wm   = (wid & 3) * 32;
    const int wn   = (wid >> 2) * 64;
    const int brow = blockIdx.y * BM;
    const int bcol = (blockIdx.x & 1) * BN;

    float c[2][8][4];
    #pragma unroll
    for (int i = 0; i < 2; i++)
        #pragma unroll
        for (int j = 0; j < 8; j++)
            #pragma unroll
            for (int r = 0; r < 4; r++) c[i][j][r] = 0.f;

    // cp.async mapping: 2 chunks of 16B (8 halves) per thread per tile per matrix
    const __half* asrc[2];
    const __half* bsrc[2];
    int aoff[2], boff[2];
    #pragma unroll
    for (int i = 0; i < 2; i++) {
        int ci = tid + i * 256;                // 0..511
        int ar = ci >> 2, akc = (ci & 3) * 8;  // A: 128 rows x 4 chunks
        int br = ci >> 4, bnc = (ci & 15) * 8; // B: 32 rows x 16 chunks
        int gr = brow + ar;
        if (gr >= M) gr = M - 1;
        asrc[i] = Ah + (size_t)gr * 256 + akc;
        bsrc[i] = B + (size_t)br * 256 + bcol + bnc;
        aoff[i] = ar * ASTR + akc;
        boff[i] = br * BSTR + bnc;
    }

    uint32_t sa0 = (uint32_t)__cvta_generic_to_shared(&sA[0][0]);
    uint32_t sa1 = (uint32_t)__cvta_generic_to_shared(&sA[1][0]);
    uint32_t sb0 = (uint32_t)__cvta_generic_to_shared(&sB[0][0]);
    uint32_t sb1 = (uint32_t)__cvta_generic_to_shared(&sB[1][0]);

    // preload tile 0
    #pragma unroll
    for (int i = 0; i < 2; i++) {
        cp_async16(sa0 + aoff[i] * 2, asrc[i]);
        cp_async16(sb0 + boff[i] * 2, bsrc[i]);
    }
    asm volatile("cp.async.commit_group;");
    asm volatile("cp.async.wait_group 0;");
    __syncthreads();

    const int lrow = lane & 15;
    const int lhi  = (lane >> 4) * 8;
    const int NSTEP = 256 / BK;   // 8

    for (int t = 0; t < NSTEP; t++) {
        const int cur = t & 1;
        const bool has_next = (t + 1 < NSTEP);
        if (has_next) {
            uint32_t da = cur ? sa0 : sa1;
            uint32_t db = cur ? sb0 : sb1;
            int k0 = (t + 1) * BK;
            #pragma unroll
            for (int i = 0; i < 2; i++) {
                cp_async16(da + aoff[i] * 2, asrc[i] + k0);
                cp_async16(db + boff[i] * 2, bsrc[i] + (size_t)k0 * 256);
            }
            asm volatile("cp.async.commit_group;");
        }

        uint32_t abase = cur ? sa1 : sa0;
        uint32_t bbase = cur ? sb1 : sb0;

        #pragma unroll
        for (int kb = 0; kb < BK; kb += 16) {
            uint32_t af[2][4];
            #pragma unroll
            for (int mt = 0; mt < 2; mt++) {
                uint32_t addr = abase + ((wm + mt * 16 + lrow) * ASTR + kb + lhi) * 2;
                asm volatile("ldmatrix.sync.aligned.m8n8.x4.shared.b16 {%0,%1,%2,%3}, [%4];"
                             : "=r"(af[mt][0]), "=r"(af[mt][1]),
                               "=r"(af[mt][2]), "=r"(af[mt][3])
                             : "r"(addr));
            }
            uint32_t bf[8][2];
            #pragma unroll
            for (int nt2 = 0; nt2 < 4; nt2++) {
                uint32_t addr = bbase + ((kb + lrow) * BSTR + wn + nt2 * 16 + lhi) * 2;
                asm volatile("ldmatrix.sync.aligned.m8n8.x4.trans.shared.b16 {%0,%1,%2,%3}, [%4];"
                             : "=r"(bf[2 * nt2][0]), "=r"(bf[2 * nt2][1]),
                               "=r"(bf[2 * nt2 + 1][0]), "=r"(bf[2 * nt2 + 1][1])
                             : "r"(addr));
            }
            #pragma unroll
            for (int mt = 0; mt < 2; mt++)
                #pragma unroll
                for (int nt = 0; nt < 8; nt++) {
                    asm volatile(
                        "mma.sync.aligned.m16n8k16.row.col.f32.f16.f16.f32 "
                        "{%0,%1,%2,%3}, {%4,%5,%6,%7}, {%8,%9}, {%0,%1,%2,%3};"
                        : "+f"(c[mt][nt][0]), "+f"(c[mt][nt][1]),
                          "+f"(c[mt][nt][2]), "+f"(c[mt][nt][3])
                        : "r"(af[mt][0]), "r"(af[mt][1]),
                          "r"(af[mt][2]), "r"(af[mt][3]),
                          "r"(bf[nt][0]), "r"(bf[nt][1]));
                }
        }

        if (has_next) asm volatile("cp.async.wait_group 0;");
        __syncthreads();
    }

    // epilogue
    const int l4 = lane & 3, l8 = lane >> 2;
    const bool is_f32 = (which == 0) || (which == 3);
    float*  Cf = qs + ((which == 3) ? 256 : 0);
    __half* Ch = kv + ((which == 2) ? 256 : 0);
    #pragma unroll
    for (int mt = 0; mt < 2; mt++) {
        #pragma unroll
        for (int half = 0; half < 2; half++) {
            int grow = brow + wm + mt * 16 + l8 + half * 8;
            if (grow < M) {
                #pragma unroll
                for (int nt = 0; nt < 8; nt++) {
                    int gcol = bcol + wn + nt * 8 + 2 * l4;
                    float ox = c[mt][nt][half * 2 + 0] + bias[gcol + 0];
                    float oy = c[mt][nt][half * 2 + 1] + bias[gcol + 1];
                    if (is_f32) {
                        *(float2*)(Cf + (size_t)grow * 512 + gcol) = make_float2(ox, oy);
                    } else {
                        *(__half2*)(Ch + (size_t)grow * 512 + gcol) = __floats2half2_rn(ox, oy);
                    }
                }
            }
        }
    }
}

// ---------------- edge attention ---------------------------------------------
// Writes next-layer features fp16 to ah; fp32 to out only when out != nullptr.
__global__ void edge_attn_kernel(const float* __restrict__ qs,
                                 const __half* __restrict__ kv,
                                 float* __restrict__ out,
                                 __half* __restrict__ ah) {
    int warp = (blockIdx.x * blockDim.x + threadIdx.x) >> 5;
    if (warp >= NN) return;
    int lane = threadIdx.x & 31;
    const int ch = lane * 8;
    const float* nb = qs + (size_t)warp * 512;

    float4 q0 = *(const float4*)(nb + ch);
    float4 q1 = *(const float4*)(nb + ch + 4);

    float d = 0.f;
    float acc[8];
    #pragma unroll
    for (int i = 0; i < 8; i++) acc[i] = 0.f;

    const int e0 = g_rowptr[warp], e1 = g_rowptr[warp + 1];
    int e = e0;

    #define LOADKV(S, KK, VV)                                                  \
        {                                                                      \
            const __half* p_ = kv + (size_t)(S) * 512 + ch;                    \
            KK = *(const uint4*)p_;                                            \
            VV = *(const uint4*)(p_ + 256);                                    \
        }
    #define DOT8(KK, P)                                                        \
        {                                                                      \
            float2 h0_ = __half22float2(*(__half2*)&KK.x);                     \
            float2 h1_ = __half22float2(*(__half2*)&KK.y);                     \
            float2 h2_ = __half22float2(*(__half2*)&KK.z);                     \
            float2 h3_ = __half22float2(*(__half2*)&KK.w);                     \
            P = q0.x*h0_.x + q0.y*h0_.y + q0.z*h1_.x + q0.w*h1_.y              \
              + q1.x*h2_.x + q1.y*h2_.y + q1.z*h3_.x + q1.w*h3_.y;             \
        }
    #define ACCV(VV, PE)                                                       \
        {                                                                      \
            float2 h0_ = __half22float2(*(__half2*)&VV.x);                     \
            float2 h1_ = __half22float2(*(__half2*)&VV.y);                     \
            float2 h2_ = __half22float2(*(__half2*)&VV.z);                     \
            float2 h3_ = __half22float2(*(__half2*)&VV.w);                     \
            acc[0] += PE * h0_.x; acc[1] += PE * h0_.y;                        \
            acc[2] += PE * h1_.x; acc[3] += PE * h1_.y;                        \
            acc[4] += PE * h2_.x; acc[5] += PE * h2_.y;                        \
            acc[6] += PE * h3_.x; acc[7] += PE * h3_.y;                        \
        }

    for (; e + 3 < e1; e += 4) {
        int s0 = g_col[e], s1 = g_col[e + 1], s2 = g_col[e + 2], s3 = g_col[e + 3];
        uint4 k0v, k1v, k2v, k3v, v0v, v1v, v2v, v3v;
        LOADKV(s0, k0v, v0v);
        LOADKV(s1, k1v, v1v);
        LOADKV(s2, k2v, v2v);
        LOADKV(s3, k3v, v3v);

        float p0, p1, p2, p3;
        DOT8(k0v, p0);
        DOT8(k1v, p1);
        DOT8(k2v, p2);
        DOT8(k3v, p3);
        p0 += __shfl_xor_sync(0xffffffff, p0, 1);
        p1 += __shfl_xor_sync(0xffffffff, p1, 1);
        p2 += __shfl_xor_sync(0xffffffff, p2, 1);
        p3 += __shfl_xor_sync(0xffffffff, p3, 1);
        p0 += __shfl_xor_sync(0xffffffff, p0, 2);
        p1 += __shfl_xor_sync(0xffffffff, p1, 2);
        p2 += __shfl_xor_sync(0xffffffff, p2, 2);
        p3 += __shfl_xor_sync(0xffffffff, p3, 2);
        p0 += __shfl_xor_sync(0xffffffff, p0, 4);
        p1 += __shfl_xor_sync(0xffffffff, p1, 4);
        p2 += __shfl_xor_sync(0xffffffff, p2, 4);
        p3 += __shfl_xor_sync(0xffffffff, p3, 4);

        float pe0 = __expf(fminf(p0 * SCALE, 85.f));
        float pe1 = __expf(fminf(p1 * SCALE, 85.f));
        float pe2 = __expf(fminf(p2 * SCALE, 85.f));
        float pe3 = __expf(fminf(p3 * SCALE, 85.f));
        d += pe0 + pe1 + pe2 + pe3;
        ACCV(v0v, pe0);
        ACCV(v1v, pe1);
        ACCV(v2v, pe2);
        ACCV(v3v, pe3);
    }

    for (; e < e1; e++) {
        int s0 = g_col[e];
        uint4 kk, vv;
        LOADKV(s0, kk, vv);
        float p;
        DOT8(kk, p);
        p += __shfl_xor_sync(0xffffffff, p, 1);
        p += __shfl_xor_sync(0xffffffff, p, 2);
        p += __shfl_xor_sync(0xffffffff, p, 4);
        float pe = __expf(fminf(p * SCALE, 85.f));
        d += pe;
        ACCV(vv, pe);
    }

    float inv = (d > 0.f) ? 1.f / d : 0.f;
    const float* sp = nb + 256 + ch;
    float4 s0v = *(const float4*)sp;
    float4 s1v = *(const float4*)(sp + 4);
    float4 o0, o1;
    o0.x = fmaxf(acc[0] * inv + s0v.x, 0.f);
    o0.y = fmaxf(acc[1] * inv + s0v.y, 0.f);
    o0.z = fmaxf(acc[2] * inv + s0v.z, 0.f);
    o0.w = fmaxf(acc[3] * inv + s0v.w, 0.f);
    o1.x = fmaxf(acc[4] * inv + s1v.x, 0.f);
    o1.y = fmaxf(acc[5] * inv + s1v.y, 0.f);
    o1.z = fmaxf(acc[6] * inv + s1v.z, 0.f);
    o1.w = fmaxf(acc[7] * inv + s1v.w, 0.f);

    // fp16 features for next layer's GEMM
    uint4 hp;
    *(__half2*)&hp.x = __floats2half2_rn(o0.x, o0.y);
    *(__half2*)&hp.y = __floats2half2_rn(o0.z, o0.w);
    *(__half2*)&hp.z = __floats2half2_rn(o1.x, o1.y);
    *(__half2*)&hp.w = __floats2half2_rn(o1.z, o1.w);
    *(uint4*)(ah + (size_t)warp * 256 + ch) = hp;

    if (out) {
        float* op = out + (size_t)warp * 256 + ch;
        *(float4*)op       = o0;
        *(float4*)(op + 4) = o1;
    }
}

// ---------------- launch ------------------------------------------------------
extern "C" void kernel_launch(void* const* d_in, const int* in_sizes, int n_in,
                              void* d_out, int out_size) {
    const float* x   = (const float*)d_in[0];
    const int*   ei  = (const int*)d_in[1];
    const float* Wq  = (const float*)d_in[2];
    const float* bq  = (const float*)d_in[3];
    const float* Wk  = (const float*)d_in[4];
    const float* bk  = (const float*)d_in[5];
    const float* Wv  = (const float*)d_in[6];
    const float* bv  = (const float*)d_in[7];
    const float* Ws  = (const float*)d_in[8];
    const float* bs  = (const float*)d_in[9];
    float* out = (float*)d_out;

    float  *qs;
    __half *kvp, *ah, *wh;
    cudaGetSymbolAddress((void**)&qs,  g_qs);
    cudaGetSymbolAddress((void**)&kvp, g_kv);
    cudaGetSymbolAddress((void**)&ah,  g_Ah);
    cudaGetSymbolAddress((void**)&wh,  g_Wh);

    convert_w_kernel<<<(LL * 4 * 65536 + 255) / 256, 256>>>(Wq, Wk, Wv, Ws, wh);
    convert_x_kernel<<<(NN * 256 + 255) / 256, 256>>>(x, ah);

    zero_counts_kernel<<<(NN + 255) / 256, 256>>>();
    count_dst_kernel<<<(EE + 255) / 256, 256>>>(ei);
    exscan_kernel<<<1, 1024>>>();
    fill_csr_kernel<<<(EE + 255) / 256, 256>>>(ei);

    dim3 gemm_grid(8, (NN + BM - 1) / BM);
    int edge_blocks = (NN + 7) / 8;

    for (int l = 0; l < LL; l++) {
        gemm_qkvs_kernel<<<gemm_grid, 256>>>(
            ah, wh + (size_t)l * 4 * 65536,
            bq + l * HC, bk + l * HC, bv + l * HC, bs + l * HC,
            qs, kvp, NN);

        float* hout = (l == LL - 1) ? out : nullptr;
        edge_attn_kernel<<<edge_blocks, 256>>>(qs, kvp, hout, ah);
    }
}

// round 9
// speedup vs baseline: 1.8298x; 1.0519x over previous
#include <cuda_runtime.h>
#include <cuda_fp16.h>
#include <math.h>
#include <stdint.h>

#define NN 50000
#define EE 800000
#define DD 256
#define HC 256
#define LL 3
#define SCALE 0.125f

// ---------------- scratch ----------------------------------------------------
__device__ float  g_qs[NN * 512];          // [q(256) | s(256)] fp32
__device__ __half g_kv[NN * 512];          // [k(256) | v(256)] fp16
__device__ __half g_Ah[NN * 256];          // current layer input features fp16
__device__ __half g_Wh[LL * 4 * 256 * 256];// fp16 weights [l][q,k,v,s][k][n]
__device__ int    g_rowptr[NN + 1];
__device__ int    g_cnt[NN];
__device__ int    g_offs[NN];
__device__ int    g_col[EE];

// ---------------- converts ----------------------------------------------------
__global__ void convert_w_kernel(const float* __restrict__ Wq, const float* __restrict__ Wk,
                                 const float* __restrict__ Wv, const float* __restrict__ Ws,
                                 __half* __restrict__ Wh) {
    int idx = blockIdx.x * blockDim.x + threadIdx.x;   // over LL*4*65536
    if (idx < LL * 4 * 65536) {
        int l = idx >> 18;
        int w = (idx >> 16) & 3;
        int off = idx & 65535;
        const float* src = (w == 0) ? Wq : (w == 1) ? Wk : (w == 2) ? Wv : Ws;
        Wh[idx] = __float2half(src[l * 65536 + off]);
    }
}

__global__ void convert_x_kernel(const float* __restrict__ x, __half* __restrict__ Ah) {
    int idx = blockIdx.x * blockDim.x + threadIdx.x;
    if (idx < NN * 256) Ah[idx] = __float2half(x[idx]);
}

// ---------------- CSR construction ------------------------------------------
__global__ void zero_counts_kernel() {
    int i = blockIdx.x * blockDim.x + threadIdx.x;
    if (i < NN) { g_cnt[i] = 0; g_offs[i] = 0; }
}

__global__ void count_dst_kernel(const int* __restrict__ edge_index) {
    int e = blockIdx.x * blockDim.x + threadIdx.x;
    if (e < EE) atomicAdd(&g_cnt[edge_index[EE + e]], 1);
}

__global__ void exscan_kernel() {
    __shared__ int warpsum[32];
    __shared__ int carry_s;
    int tid = threadIdx.x, lane = tid & 31, wid = tid >> 5;
    if (tid == 0) carry_s = 0;
    __syncthreads();
    for (int base = 0; base < NN; base += 1024) {
        int i = base + tid;
        int val = (i < NN) ? g_cnt[i] : 0;
        int x = val;
        #pragma unroll
        for (int off = 1; off < 32; off <<= 1) {
            int y = __shfl_up_sync(0xffffffff, x, off);
            if (lane >= off) x += y;
        }
        if (lane == 31) warpsum[wid] = x;
        __syncthreads();
        if (wid == 0) {
            int w = warpsum[lane];
            #pragma unroll
            for (int off = 1; off < 32; off <<= 1) {
                int y = __shfl_up_sync(0xffffffff, w, off);
                if (lane >= off) w += y;
            }
            warpsum[lane] = w;
        }
        __syncthreads();
        int incl = x + (wid > 0 ? warpsum[wid - 1] : 0);
        int c = carry_s;
        if (i < NN) g_rowptr[i] = c + incl - val;
        __syncthreads();
        if (tid == 1023) carry_s = c + incl;
        __syncthreads();
    }
    if (tid == 0) g_rowptr[NN] = carry_s;
}

__global__ void fill_csr_kernel(const int* __restrict__ edge_index) {
    int e = blockIdx.x * blockDim.x + threadIdx.x;
    if (e < EE) {
        int s = edge_index[e];
        int d = edge_index[EE + e];
        int pos = g_rowptr[d] + atomicAdd(&g_offs[d], 1);
        g_col[pos] = s;
    }
}

// ---------------- FP16 GEMM: 3-stage cp.async pipeline, BK=32 ----------------
#define BM 128
#define BN 128
#define BK 32
#define ASTR 40     // halfs per A row (32+8): 20r%32 distinct over 8 rows
#define BSTR 136    // halfs per B row (128+8): 34k%32 -> 2k%32... 136/2=68 words? (k*68)%32 = 4k%32 distinct
#define STAGES 3
#define SA_STAGE (BM * ASTR)               // halfs
#define SB_STAGE (BK * BSTR)               // halfs
#define GEMM_SMEM ((STAGES * (SA_STAGE + SB_STAGE)) * 2)   // bytes = 56832

__device__ __forceinline__ void cp_async16(uint32_t dst, const void* src) {
    asm volatile("cp.async.cg.shared.global [%0], [%1], 16;" :: "r"(dst), "l"(src));
}

__global__ __launch_bounds__(256, 2)
void gemm_qkvs_kernel(const __half* __restrict__ Ah,
                      const __half* __restrict__ Wl,   // this layer: 4 x [256][256] fp16
                      const float* __restrict__ b0, const float* __restrict__ b1,
                      const float* __restrict__ b2, const float* __restrict__ b3,
                      float* __restrict__ qs, __half* __restrict__ kv, int M) {
    extern __shared__ __half smh[];
    __half* sA = smh;                          // STAGES * SA_STAGE
    __half* sB = smh + STAGES * SA_STAGE;      // STAGES * SB_STAGE

    const int which = blockIdx.x >> 1;
    const __half* B   = Wl + which * 65536;
    const float* bias = (which == 0) ? b0 : (which == 1) ? b1 : (which == 2) ? b2 : b3;

    const int tid  = threadIdx.x;
    const int lane = tid & 31;
    const int wid  = tid >> 5;
    const int wm   = (wid & 3) * 32;
    const int wn   = (wid >> 2) * 64;
    const int brow = blockIdx.y * BM;
    const int bcol = (blockIdx.x & 1) * BN;

    float c[2][8][4];
    #pragma unroll
    for (int i = 0; i < 2; i++)
        #pragma unroll
        for (int j = 0; j < 8; j++)
            #pragma unroll
            for (int r = 0; r < 4; r++) c[i][j][r] = 0.f;

    // cp.async mapping: 2 chunks of 16B (8 halves) per thread per tile per matrix
    const __half* asrc[2];
    const __half* bsrc[2];
    int aoff[2], boff[2];
    #pragma unroll
    for (int i = 0; i < 2; i++) {
        int ci = tid + i * 256;                // 0..511
        int ar = ci >> 2, akc = (ci & 3) * 8;  // A: 128 rows x 4 chunks
        int br = ci >> 4, bnc = (ci & 15) * 8; // B: 32 rows x 16 chunks
        int gr = brow + ar;
        if (gr >= M) gr = M - 1;
        asrc[i] = Ah + (size_t)gr * 256 + akc;
        bsrc[i] = B + (size_t)br * 256 + bcol + bnc;
        aoff[i] = ar * ASTR + akc;
        boff[i] = br * BSTR + bnc;
    }

    uint32_t sabase = (uint32_t)__cvta_generic_to_shared(sA);
    uint32_t sbbase = (uint32_t)__cvta_generic_to_shared(sB);

    const int NSTEP = 256 / BK;   // 8

    // preload tiles 0,1 into stages 0,1
    #pragma unroll
    for (int p = 0; p < 2; p++) {
        int k0 = p * BK;
        #pragma unroll
        for (int i = 0; i < 2; i++) {
            cp_async16(sabase + (p * SA_STAGE + aoff[i]) * 2, asrc[i] + k0);
            cp_async16(sbbase + (p * SB_STAGE + boff[i]) * 2, bsrc[i] + (size_t)k0 * 256);
        }
        asm volatile("cp.async.commit_group;");
    }

    const int lrow = lane & 15;
    const int lhi  = (lane >> 4) * 8;

    int st_c = 0;   // compute stage
    int st_p = 2;   // prefetch stage
    for (int t = 0; t < NSTEP; t++) {
        asm volatile("cp.async.wait_group 1;");   // tile t resident
        __syncthreads();

        // prefetch tile t+2 (overlaps with compute below)
        if (t + 2 < NSTEP) {
            int k0 = (t + 2) * BK;
            #pragma unroll
            for (int i = 0; i < 2; i++) {
                cp_async16(sabase + (st_p * SA_STAGE + aoff[i]) * 2, asrc[i] + k0);
                cp_async16(sbbase + (st_p * SB_STAGE + boff[i]) * 2, bsrc[i] + (size_t)k0 * 256);
            }
        }
        asm volatile("cp.async.commit_group;");

        uint32_t abase = sabase + st_c * SA_STAGE * 2;
        uint32_t bbase = sbbase + st_c * SB_STAGE * 2;

        #pragma unroll
        for (int kb = 0; kb < BK; kb += 16) {
            uint32_t af[2][4];
            #pragma unroll
            for (int mt = 0; mt < 2; mt++) {
                uint32_t addr = abase + ((wm + mt * 16 + lrow) * ASTR + kb + lhi) * 2;
                asm volatile("ldmatrix.sync.aligned.m8n8.x4.shared.b16 {%0,%1,%2,%3}, [%4];"
                             : "=r"(af[mt][0]), "=r"(af[mt][1]),
                               "=r"(af[mt][2]), "=r"(af[mt][3])
                             : "r"(addr));
            }
            uint32_t bf[8][2];
            #pragma unroll
            for (int nt2 = 0; nt2 < 4; nt2++) {
                uint32_t addr = bbase + ((kb + lrow) * BSTR + wn + nt2 * 16 + lhi) * 2;
                asm volatile("ldmatrix.sync.aligned.m8n8.x4.trans.shared.b16 {%0,%1,%2,%3}, [%4];"
                             : "=r"(bf[2 * nt2][0]), "=r"(bf[2 * nt2][1]),
                               "=r"(bf[2 * nt2 + 1][0]), "=r"(bf[2 * nt2 + 1][1])
                             : "r"(addr));
            }
            #pragma unroll
            for (int mt = 0; mt < 2; mt++)
                #pragma unroll
                for (int nt = 0; nt < 8; nt++) {
                    asm volatile(
                        "mma.sync.aligned.m16n8k16.row.col.f32.f16.f16.f32 "
                        "{%0,%1,%2,%3}, {%4,%5,%6,%7}, {%8,%9}, {%0,%1,%2,%3};"
                        : "+f"(c[mt][nt][0]), "+f"(c[mt][nt][1]),
                          "+f"(c[mt][nt][2]), "+f"(c[mt][nt][3])
                        : "r"(af[mt][0]), "r"(af[mt][1]),
                          "r"(af[mt][2]), "r"(af[mt][3]),
                          "r"(bf[nt][0]), "r"(bf[nt][1]));
                }
        }

        st_c = (st_c == STAGES - 1) ? 0 : st_c + 1;
        st_p = (st_p == STAGES - 1) ? 0 : st_p + 1;
    }

    // epilogue
    const int l4 = lane & 3, l8 = lane >> 2;
    const bool is_f32 = (which == 0) || (which == 3);
    float*  Cf = qs + ((which == 3) ? 256 : 0);
    __half* Ch = kv + ((which == 2) ? 256 : 0);
    #pragma unroll
    for (int mt = 0; mt < 2; mt++) {
        #pragma unroll
        for (int half = 0; half < 2; half++) {
            int grow = brow + wm + mt * 16 + l8 + half * 8;
            if (grow < M) {
                #pragma unroll
                for (int nt = 0; nt < 8; nt++) {
                    int gcol = bcol + wn + nt * 8 + 2 * l4;
                    float ox = c[mt][nt][half * 2 + 0] + bias[gcol + 0];
                    float oy = c[mt][nt][half * 2 + 1] + bias[gcol + 1];
                    if (is_f32) {
                        *(float2*)(Cf + (size_t)grow * 512 + gcol) = make_float2(ox, oy);
                    } else {
                        *(__half2*)(Ch + (size_t)grow * 512 + gcol) = __floats2half2_rn(ox, oy);
                    }
                }
            }
        }
    }
}

// ---------------- edge attention ---------------------------------------------
__global__ void edge_attn_kernel(const float* __restrict__ qs,
                                 const __half* __restrict__ kv,
                                 float* __restrict__ out,
                                 __half* __restrict__ ah) {
    int warp = (blockIdx.x * blockDim.x + threadIdx.x) >> 5;
    if (warp >= NN) return;
    int lane = threadIdx.x & 31;
    const int ch = lane * 8;
    const float* nb = qs + (size_t)warp * 512;

    float4 q0 = *(const float4*)(nb + ch);
    float4 q1 = *(const float4*)(nb + ch + 4);

    float d = 0.f;
    float acc[8];
    #pragma unroll
    for (int i = 0; i < 8; i++) acc[i] = 0.f;

    const int e0 = g_rowptr[warp], e1 = g_rowptr[warp + 1];
    int e = e0;

    #define LOADKV(S, KK, VV)                                                  \
        {                                                                      \
            const __half* p_ = kv + (size_t)(S) * 512 + ch;                    \
            KK = *(const uint4*)p_;                                            \
            VV = *(const uint4*)(p_ + 256);                                    \
        }
    #define DOT8(KK, P)                                                        \
        {                                                                      \
            float2 h0_ = __half22float2(*(__half2*)&KK.x);                     \
            float2 h1_ = __half22float2(*(__half2*)&KK.y);                     \
            float2 h2_ = __half22float2(*(__half2*)&KK.z);                     \
            float2 h3_ = __half22float2(*(__half2*)&KK.w);                     \
            P = q0.x*h0_.x + q0.y*h0_.y + q0.z*h1_.x + q0.w*h1_.y              \
              + q1.x*h2_.x + q1.y*h2_.y + q1.z*h3_.x + q1.w*h3_.y;             \
        }
    #define ACCV(VV, PE)                                                       \
        {                                                                      \
            float2 h0_ = __half22float2(*(__half2*)&VV.x);                     \
            float2 h1_ = __half22float2(*(__half2*)&VV.y);                     \
            float2 h2_ = __half22float2(*(__half2*)&VV.z);                     \
            float2 h3_ = __half22float2(*(__half2*)&VV.w);                     \
            acc[0] += PE * h0_.x; acc[1] += PE * h0_.y;                        \
            acc[2] += PE * h1_.x; acc[3] += PE * h1_.y;                        \
            acc[4] += PE * h2_.x; acc[5] += PE * h2_.y;                        \
            acc[6] += PE * h3_.x; acc[7] += PE * h3_.y;                        \
        }

    for (; e + 3 < e1; e += 4) {
        int s0 = g_col[e], s1 = g_col[e + 1], s2 = g_col[e + 2], s3 = g_col[e + 3];
        uint4 k0v, k1v, k2v, k3v, v0v, v1v, v2v, v3v;
        LOADKV(s0, k0v, v0v);
        LOADKV(s1, k1v, v1v);
        LOADKV(s2, k2v, v2v);
        LOADKV(s3, k3v, v3v);

        float p0, p1, p2, p3;
        DOT8(k0v, p0);
        DOT8(k1v, p1);
        DOT8(k2v, p2);
        DOT8(k3v, p3);
        p0 += __shfl_xor_sync(0xffffffff, p0, 1);
        p1 += __shfl_xor_sync(0xffffffff, p1, 1);
        p2 += __shfl_xor_sync(0xffffffff, p2, 1);
        p3 += __shfl_xor_sync(0xffffffff, p3, 1);
        p0 += __shfl_xor_sync(0xffffffff, p0, 2);
        p1 += __shfl_xor_sync(0xffffffff, p1, 2);
        p2 += __shfl_xor_sync(0xffffffff, p2, 2);
        p3 += __shfl_xor_sync(0xffffffff, p3, 2);
        p0 += __shfl_xor_sync(0xffffffff, p0, 4);
        p1 += __shfl_xor_sync(0xffffffff, p1, 4);
        p2 += __shfl_xor_sync(0xffffffff, p2, 4);
        p3 += __shfl_xor_sync(0xffffffff, p3, 4);

        float pe0 = __expf(fminf(p0 * SCALE, 85.f));
        float pe1 = __expf(fminf(p1 * SCALE, 85.f));
        float pe2 = __expf(fminf(p2 * SCALE, 85.f));
        float pe3 = __expf(fminf(p3 * SCALE, 85.f));
        d += pe0 + pe1 + pe2 + pe3;
        ACCV(v0v, pe0);
        ACCV(v1v, pe1);
        ACCV(v2v, pe2);
        ACCV(v3v, pe3);
    }

    for (; e < e1; e++) {
        int s0 = g_col[e];
        uint4 kk, vv;
        LOADKV(s0, kk, vv);
        float p;
        DOT8(kk, p);
        p += __shfl_xor_sync(0xffffffff, p, 1);
        p += __shfl_xor_sync(0xffffffff, p, 2);
        p += __shfl_xor_sync(0xffffffff, p, 4);
        float pe = __expf(fminf(p * SCALE, 85.f));
        d += pe;
        ACCV(vv, pe);
    }

    float inv = (d > 0.f) ? 1.f / d : 0.f;
    const float* sp = nb + 256 + ch;
    float4 s0v = *(const float4*)sp;
    float4 s1v = *(const float4*)(sp + 4);
    float4 o0, o1;
    o0.x = fmaxf(acc[0] * inv + s0v.x, 0.f);
    o0.y = fmaxf(acc[1] * inv + s0v.y, 0.f);
    o0.z = fmaxf(acc[2] * inv + s0v.z, 0.f);
    o0.w = fmaxf(acc[3] * inv + s0v.w, 0.f);
    o1.x = fmaxf(acc[4] * inv + s1v.x, 0.f);
    o1.y = fmaxf(acc[5] * inv + s1v.y, 0.f);
    o1.z = fmaxf(acc[6] * inv + s1v.z, 0.f);
    o1.w = fmaxf(acc[7] * inv + s1v.w, 0.f);

    uint4 hp;
    *(__half2*)&hp.x = __floats2half2_rn(o0.x, o0.y);
    *(__half2*)&hp.y = __floats2half2_rn(o0.z, o0.w);
    *(__half2*)&hp.z = __floats2half2_rn(o1.x, o1.y);
    *(__half2*)&hp.w = __floats2half2_rn(o1.z, o1.w);
    *(uint4*)(ah + (size_t)warp * 256 + ch) = hp;

    if (out) {
        float* op = out + (size_t)warp * 256 + ch;
        *(float4*)op       = o0;
        *(float4*)(op + 4) = o1;
    }
}

// ---------------- launch ------------------------------------------------------
extern "C" void kernel_launch(void* const* d_in, const int* in_sizes, int n_in,
                              void* d_out, int out_size) {
    const float* x   = (const float*)d_in[0];
    const int*   ei  = (const int*)d_in[1];
    const float* Wq  = (const float*)d_in[2];
    const float* bq  = (const float*)d_in[3];
    const float* Wk  = (const float*)d_in[4];
    const float* bk  = (const float*)d_in[5];
    const float* Wv  = (const float*)d_in[6];
    const float* bv  = (const float*)d_in[7];
    const float* Ws  = (const float*)d_in[8];
    const float* bs  = (const float*)d_in[9];
    float* out = (float*)d_out;

    float  *qs;
    __half *kvp, *ah, *wh;
    cudaGetSymbolAddress((void**)&qs,  g_qs);
    cudaGetSymbolAddress((void**)&kvp, g_kv);
    cudaGetSymbolAddress((void**)&ah,  g_Ah);
    cudaGetSymbolAddress((void**)&wh,  g_Wh);

    static bool attr_set = false;
    if (!attr_set) {
        cudaFuncSetAttribute(gemm_qkvs_kernel,
                             cudaFuncAttributeMaxDynamicSharedMemorySize, GEMM_SMEM);
        attr_set = true;
    }

    convert_w_kernel<<<(LL * 4 * 65536 + 255) / 256, 256>>>(Wq, Wk, Wv, Ws, wh);
    convert_x_kernel<<<(NN * 256 + 255) / 256, 256>>>(x, ah);

    zero_counts_kernel<<<(NN + 255) / 256, 256>>>();
    count_dst_kernel<<<(EE + 255) / 256, 256>>>(ei);
    exscan_kernel<<<1, 1024>>>();
    fill_csr_kernel<<<(EE + 255) / 256, 256>>>(ei);

    dim3 gemm_grid(8, (NN + BM - 1) / BM);
    int edge_blocks = (NN + 7) / 8;

    for (int l = 0; l < LL; l++) {
        gemm_qkvs_kernel<<<gemm_grid, 256, GEMM_SMEM>>>(
            ah, wh + (size_t)l * 4 * 65536,
            bq + l * HC, bk + l * HC, bv + l * HC, bs + l * HC,
            qs, kvp, NN);

        float* hout = (l == LL - 1) ? out : nullptr;
        edge_attn_kernel<<<edge_blocks, 256>>>(qs, kvp, hout, ah);
    }
}

// round 10
// speedup vs baseline: 1.9465x; 1.0638x over previous
#include <cuda_runtime.h>
#include <cuda_fp16.h>
#include <math.h>
#include <stdint.h>

#define NN 50000
#define EE 800000
#define DD 256
#define HC 256
#define LL 3
#define SCALE 0.125f

// ---------------- scratch ----------------------------------------------------
__device__ float  g_qs[NN * 512];          // [q(256) | s(256)] fp32
__device__ __half g_kv[NN * 512];          // [k(256) | v(256)] fp16
__device__ __half g_Ah[NN * 256];          // current layer input features fp16
__device__ __half g_Wh[LL * 4 * 256 * 256];// fp16 weights [l][q,k,v,s][k][n]
__device__ int    g_rowptr[NN + 1];
__device__ int    g_cnt[NN];
__device__ int    g_offs[NN];
__device__ int    g_col[EE];
__device__ int    g_bsum[64];
__device__ int    g_boff[64];

// ---------------- converts ----------------------------------------------------
__global__ void convert_w_kernel(const float* __restrict__ Wq, const float* __restrict__ Wk,
                                 const float* __restrict__ Wv, const float* __restrict__ Ws,
                                 __half* __restrict__ Wh) {
    int idx = blockIdx.x * blockDim.x + threadIdx.x;
    if (idx < LL * 4 * 65536) {
        int l = idx >> 18;
        int w = (idx >> 16) & 3;
        int off = idx & 65535;
        const float* src = (w == 0) ? Wq : (w == 1) ? Wk : (w == 2) ? Wv : Ws;
        Wh[idx] = __float2half(src[l * 65536 + off]);
    }
}

__global__ void convert_x_kernel(const float* __restrict__ x, __half* __restrict__ Ah) {
    int idx = blockIdx.x * blockDim.x + threadIdx.x;
    if (idx < NN * 256) Ah[idx] = __float2half(x[idx]);
}

// ---------------- CSR construction ------------------------------------------
__global__ void zero_counts_kernel() {
    int i = blockIdx.x * blockDim.x + threadIdx.x;
    if (i < NN) { g_cnt[i] = 0; g_offs[i] = 0; }
}

__global__ void count_dst_kernel(const int* __restrict__ edge_index) {
    int e = blockIdx.x * blockDim.x + threadIdx.x;
    if (e < EE) atomicAdd(&g_cnt[edge_index[EE + e]], 1);
}

// multi-block scan, phase 1: per-block (1024) exclusive scan + block sums
__global__ void scan1_kernel() {
    __shared__ int warpsum[32];
    int tid = threadIdx.x, lane = tid & 31, wid = tid >> 5;
    int i = blockIdx.x * 1024 + tid;
    int val = (i < NN) ? g_cnt[i] : 0;
    int x = val;
    #pragma unroll
    for (int off = 1; off < 32; off <<= 1) {
        int y = __shfl_up_sync(0xffffffff, x, off);
        if (lane >= off) x += y;
    }
    if (lane == 31) warpsum[wid] = x;
    __syncthreads();
    if (wid == 0) {
        int w = warpsum[lane];
        #pragma unroll
        for (int off = 1; off < 32; off <<= 1) {
            int y = __shfl_up_sync(0xffffffff, w, off);
            if (lane >= off) w += y;
        }
        warpsum[lane] = w;
    }
    __syncthreads();
    int incl = x + (wid > 0 ? warpsum[wid - 1] : 0);
    if (i < NN) g_rowptr[i] = incl - val;
    if (tid == 1023) g_bsum[blockIdx.x] = incl;
}

// phase 2: 1 thread scans the 49 block sums
__global__ void scan2_kernel(int nblocks) {
    if (threadIdx.x == 0) {
        int run = 0;
        for (int b = 0; b < nblocks; b++) {
            g_boff[b] = run;
            run += g_bsum[b];
        }
        g_rowptr[NN] = run;
    }
}

// phase 3: add block offsets
__global__ void scan3_kernel() {
    int i = blockIdx.x * 1024 + threadIdx.x;
    if (i < NN) g_rowptr[i] += g_boff[blockIdx.x];
}

__global__ void fill_csr_kernel(const int* __restrict__ edge_index) {
    int e = blockIdx.x * blockDim.x + threadIdx.x;
    if (e < EE) {
        int s = edge_index[e];
        int d = edge_index[EE + e];
        int pos = g_rowptr[d] + atomicAdd(&g_offs[d], 1);
        g_col[pos] = s;
    }
}

// ---------------- FP16 GEMM: 3-stage cp.async pipeline, BK=32 ----------------
#define BM 128
#define BN 128
#define BK 32
#define ASTR 40
#define BSTR 136
#define STAGES 3
#define SA_STAGE (BM * ASTR)
#define SB_STAGE (BK * BSTR)
#define GEMM_SMEM ((STAGES * (SA_STAGE + SB_STAGE)) * 2)

__device__ __forceinline__ void cp_async16(uint32_t dst, const void* src) {
    asm volatile("cp.async.cg.shared.global [%0], [%1], 16;" :: "r"(dst), "l"(src));
}

__global__ __launch_bounds__(256, 2)
void gemm_qkvs_kernel(const __half* __restrict__ Ah,
                      const __half* __restrict__ Wl,
                      const float* __restrict__ b0, const float* __restrict__ b1,
                      const float* __restrict__ b2, const float* __restrict__ b3,
                      float* __restrict__ qs, __half* __restrict__ kv, int M) {
    extern __shared__ __half smh[];
    __half* sA = smh;
    __half* sB = smh + STAGES * SA_STAGE;

    const int which = blockIdx.x >> 1;
    const __half* B   = Wl + which * 65536;
    const float* bias = (which == 0) ? b0 : (which == 1) ? b1 : (which == 2) ? b2 : b3;

    const int tid  = threadIdx.x;
    const int lane = tid & 31;
    const int wid  = tid >> 5;
    const int wm   = (wid & 3) * 32;
    const int wn   = (wid >> 2) * 64;
    const int brow = blockIdx.y * BM;
    const int bcol = (blockIdx.x & 1) * BN;

    float c[2][8][4];
    #pragma unroll
    for (int i = 0; i < 2; i++)
        #pragma unroll
        for (int j = 0; j < 8; j++)
            #pragma unroll
            for (int r = 0; r < 4; r++) c[i][j][r] = 0.f;

    const __half* asrc[2];
    const __half* bsrc[2];
    int aoff[2], boff[2];
    #pragma unroll
    for (int i = 0; i < 2; i++) {
        int ci = tid + i * 256;
        int ar = ci >> 2, akc = (ci & 3) * 8;
        int br = ci >> 4, bnc = (ci & 15) * 8;
        int gr = brow + ar;
        if (gr >= M) gr = M - 1;
        asrc[i] = Ah + (size_t)gr * 256 + akc;
        bsrc[i] = B + (size_t)br * 256 + bcol + bnc;
        aoff[i] = ar * ASTR + akc;
        boff[i] = br * BSTR + bnc;
    }

    uint32_t sabase = (uint32_t)__cvta_generic_to_shared(sA);
    uint32_t sbbase = (uint32_t)__cvta_generic_to_shared(sB);

    const int NSTEP = 256 / BK;   // 8

    #pragma unroll
    for (int p = 0; p < 2; p++) {
        int k0 = p * BK;
        #pragma unroll
        for (int i = 0; i < 2; i++) {
            cp_async16(sabase + (p * SA_STAGE + aoff[i]) * 2, asrc[i] + k0);
            cp_async16(sbbase + (p * SB_STAGE + boff[i]) * 2, bsrc[i] + (size_t)k0 * 256);
        }
        asm volatile("cp.async.commit_group;");
    }

    const int lrow = lane & 15;
    const int lhi  = (lane >> 4) * 8;

    int st_c = 0;
    int st_p = 2;
    for (int t = 0; t < NSTEP; t++) {
        asm volatile("cp.async.wait_group 1;");
        __syncthreads();

        if (t + 2 < NSTEP) {
            int k0 = (t + 2) * BK;
            #pragma unroll
            for (int i = 0; i < 2; i++) {
                cp_async16(sabase + (st_p * SA_STAGE + aoff[i]) * 2, asrc[i] + k0);
                cp_async16(sbbase + (st_p * SB_STAGE + boff[i]) * 2, bsrc[i] + (size_t)k0 * 256);
            }
        }
        asm volatile("cp.async.commit_group;");

        uint32_t abase = sabase + st_c * SA_STAGE * 2;
        uint32_t bbase = sbbase + st_c * SB_STAGE * 2;

        #pragma unroll
        for (int kb = 0; kb < BK; kb += 16) {
            uint32_t af[2][4];
            #pragma unroll
            for (int mt = 0; mt < 2; mt++) {
                uint32_t addr = abase + ((wm + mt * 16 + lrow) * ASTR + kb + lhi) * 2;
                asm volatile("ldmatrix.sync.aligned.m8n8.x4.shared.b16 {%0,%1,%2,%3}, [%4];"
                             : "=r"(af[mt][0]), "=r"(af[mt][1]),
                               "=r"(af[mt][2]), "=r"(af[mt][3])
                             : "r"(addr));
            }
            uint32_t bf[8][2];
            #pragma unroll
            for (int nt2 = 0; nt2 < 4; nt2++) {
                uint32_t addr = bbase + ((kb + lrow) * BSTR + wn + nt2 * 16 + lhi) * 2;
                asm volatile("ldmatrix.sync.aligned.m8n8.x4.trans.shared.b16 {%0,%1,%2,%3}, [%4];"
                             : "=r"(bf[2 * nt2][0]), "=r"(bf[2 * nt2][1]),
                               "=r"(bf[2 * nt2 + 1][0]), "=r"(bf[2 * nt2 + 1][1])
                             : "r"(addr));
            }
            #pragma unroll
            for (int mt = 0; mt < 2; mt++)
                #pragma unroll
                for (int nt = 0; nt < 8; nt++) {
                    asm volatile(
                        "mma.sync.aligned.m16n8k16.row.col.f32.f16.f16.f32 "
                        "{%0,%1,%2,%3}, {%4,%5,%6,%7}, {%8,%9}, {%0,%1,%2,%3};"
                        : "+f"(c[mt][nt][0]), "+f"(c[mt][nt][1]),
                          "+f"(c[mt][nt][2]), "+f"(c[mt][nt][3])
                        : "r"(af[mt][0]), "r"(af[mt][1]),
                          "r"(af[mt][2]), "r"(af[mt][3]),
                          "r"(bf[nt][0]), "r"(bf[nt][1]));
                }
        }

        st_c = (st_c == STAGES - 1) ? 0 : st_c + 1;
        st_p = (st_p == STAGES - 1) ? 0 : st_p + 1;
    }

    const int l4 = lane & 3, l8 = lane >> 2;
    const bool is_f32 = (which == 0) || (which == 3);
    float*  Cf = qs + ((which == 3) ? 256 : 0);
    __half* Ch = kv + ((which == 2) ? 256 : 0);
    #pragma unroll
    for (int mt = 0; mt < 2; mt++) {
        #pragma unroll
        for (int half = 0; half < 2; half++) {
            int grow = brow + wm + mt * 16 + l8 + half * 8;
            if (grow < M) {
                #pragma unroll
                for (int nt = 0; nt < 8; nt++) {
                    int gcol = bcol + wn + nt * 8 + 2 * l4;
                    float ox = c[mt][nt][half * 2 + 0] + bias[gcol + 0];
                    float oy = c[mt][nt][half * 2 + 1] + bias[gcol + 1];
                    if (is_f32) {
                        *(float2*)(Cf + (size_t)grow * 512 + gcol) = make_float2(ox, oy);
                    } else {
                        *(__half2*)(Ch + (size_t)grow * 512 + gcol) = __floats2half2_rn(ox, oy);
                    }
                }
            }
        }
    }
}

// ---------------- edge attention ---------------------------------------------
__global__ void edge_attn_kernel(const float* __restrict__ qs,
                                 const __half* __restrict__ kv,
                                 float* __restrict__ out,
                                 __half* __restrict__ ah) {
    int warp = (blockIdx.x * blockDim.x + threadIdx.x) >> 5;
    if (warp >= NN) return;
    int lane = threadIdx.x & 31;
    const int ch = lane * 8;
    const float* nb = qs + (size_t)warp * 512;

    float4 q0 = *(const float4*)(nb + ch);
    float4 q1 = *(const float4*)(nb + ch + 4);

    float d = 0.f;
    float acc[8];
    #pragma unroll
    for (int i = 0; i < 8; i++) acc[i] = 0.f;

    const int e0 = g_rowptr[warp], e1 = g_rowptr[warp + 1];
    int e = e0;

    #define LOADKV(S, KK, VV)                                                  \
        {                                                                      \
            const __half* p_ = kv + (size_t)(S) * 512 + ch;                    \
            KK = *(const uint4*)p_;                                            \
            VV = *(const uint4*)(p_ + 256);                                    \
        }
    #define DOT8(KK, P)                                                        \
        {                                                                      \
            float2 h0_ = __half22float2(*(__half2*)&KK.x);                     \
            float2 h1_ = __half22float2(*(__half2*)&KK.y);                     \
            float2 h2_ = __half22float2(*(__half2*)&KK.z);                     \
            float2 h3_ = __half22float2(*(__half2*)&KK.w);                     \
            P = q0.x*h0_.x + q0.y*h0_.y + q0.z*h1_.x + q0.w*h1_.y              \
              + q1.x*h2_.x + q1.y*h2_.y + q1.z*h3_.x + q1.w*h3_.y;             \
        }
    #define ACCV(VV, PE)                                                       \
        {                                                                      \
            float2 h0_ = __half22float2(*(__half2*)&VV.x);                     \
            float2 h1_ = __half22float2(*(__half2*)&VV.y);                     \
            float2 h2_ = __half22float2(*(__half2*)&VV.z);                     \
            float2 h3_ = __half22float2(*(__half2*)&VV.w);                     \
            acc[0] += PE * h0_.x; acc[1] += PE * h0_.y;                        \
            acc[2] += PE * h1_.x; acc[3] += PE * h1_.y;                        \
            acc[4] += PE * h2_.x; acc[5] += PE * h2_.y;                        \
            acc[6] += PE * h3_.x; acc[7] += PE * h3_.y;                        \
        }

    for (; e + 3 < e1; e += 4) {
        int s0 = g_col[e], s1 = g_col[e + 1], s2 = g_col[e + 2], s3 = g_col[e + 3];
        uint4 k0v, k1v, k2v, k3v, v0v, v1v, v2v, v3v;
        LOADKV(s0, k0v, v0v);
        LOADKV(s1, k1v, v1v);
        LOADKV(s2, k2v, v2v);
        LOADKV(s3, k3v, v3v);

        float p0, p1, p2, p3;
        DOT8(k0v, p0);
        DOT8(k1v, p1);
        DOT8(k2v, p2);
        DOT8(k3v, p3);
        p0 += __shfl_xor_sync(0xffffffff, p0, 1);
        p1 += __shfl_xor_sync(0xffffffff, p1, 1);
        p2 += __shfl_xor_sync(0xffffffff, p2, 1);
        p3 += __shfl_xor_sync(0xffffffff, p3, 1);
        p0 += __shfl_xor_sync(0xffffffff, p0, 2);
        p1 += __shfl_xor_sync(0xffffffff, p1, 2);
        p2 += __shfl_xor_sync(0xffffffff, p2, 2);
        p3 += __shfl_xor_sync(0xffffffff, p3, 2);
        p0 += __shfl_xor_sync(0xffffffff, p0, 4);
        p1 += __shfl_xor_sync(0xffffffff, p1, 4);
        p2 += __shfl_xor_sync(0xffffffff, p2, 4);
        p3 += __shfl_xor_sync(0xffffffff, p3, 4);

        float pe0 = __expf(fminf(p0 * SCALE, 85.f));
        float pe1 = __expf(fminf(p1 * SCALE, 85.f));
        float pe2 = __expf(fminf(p2 * SCALE, 85.f));
        float pe3 = __expf(fminf(p3 * SCALE, 85.f));
        d += pe0 + pe1 + pe2 + pe3;
        ACCV(v0v, pe0);
        ACCV(v1v, pe1);
        ACCV(v2v, pe2);
        ACCV(v3v, pe3);
    }

    for (; e < e1; e++) {
        int s0 = g_col[e];
        uint4 kk, vv;
        LOADKV(s0, kk, vv);
        float p;
        DOT8(kk, p);
        p += __shfl_xor_sync(0xffffffff, p, 1);
        p += __shfl_xor_sync(0xffffffff, p, 2);
        p += __shfl_xor_sync(0xffffffff, p, 4);
        float pe = __expf(fminf(p * SCALE, 85.f));
        d += pe;
        ACCV(vv, pe);
    }

    float inv = (d > 0.f) ? 1.f / d : 0.f;
    const float* sp = nb + 256 + ch;
    float4 s0v = *(const float4*)sp;
    float4 s1v = *(const float4*)(sp + 4);
    float4 o0, o1;
    o0.x = fmaxf(acc[0] * inv + s0v.x, 0.f);
    o0.y = fmaxf(acc[1] * inv + s0v.y, 0.f);
    o0.z = fmaxf(acc[2] * inv + s0v.z, 0.f);
    o0.w = fmaxf(acc[3] * inv + s0v.w, 0.f);
    o1.x = fmaxf(acc[4] * inv + s1v.x, 0.f);
    o1.y = fmaxf(acc[5] * inv + s1v.y, 0.f);
    o1.z = fmaxf(acc[6] * inv + s1v.z, 0.f);
    o1.w = fmaxf(acc[7] * inv + s1v.w, 0.f);

    uint4 hp;
    *(__half2*)&hp.x = __floats2half2_rn(o0.x, o0.y);
    *(__half2*)&hp.y = __floats2half2_rn(o0.z, o0.w);
    *(__half2*)&hp.z = __floats2half2_rn(o1.x, o1.y);
    *(__half2*)&hp.w = __floats2half2_rn(o1.z, o1.w);
    *(uint4*)(ah + (size_t)warp * 256 + ch) = hp;

    if (out) {
        float* op = out + (size_t)warp * 256 + ch;
        *(float4*)op       = o0;
        *(float4*)(op + 4) = o1;
    }
}

// ---------------- launch ------------------------------------------------------
extern "C" void kernel_launch(void* const* d_in, const int* in_sizes, int n_in,
                              void* d_out, int out_size) {
    const float* x   = (const float*)d_in[0];
    const int*   ei  = (const int*)d_in[1];
    const float* Wq  = (const float*)d_in[2];
    const float* bq  = (const float*)d_in[3];
    const float* Wk  = (const float*)d_in[4];
    const float* bk  = (const float*)d_in[5];
    const float* Wv  = (const float*)d_in[6];
    const float* bv  = (const float*)d_in[7];
    const float* Ws  = (const float*)d_in[8];
    const float* bs  = (const float*)d_in[9];
    float* out = (float*)d_out;

    float  *qs;
    __half *kvp, *ah, *wh;
    cudaGetSymbolAddress((void**)&qs,  g_qs);
    cudaGetSymbolAddress((void**)&kvp, g_kv);
    cudaGetSymbolAddress((void**)&ah,  g_Ah);
    cudaGetSymbolAddress((void**)&wh,  g_Wh);

    static bool init_done = false;
    static cudaStream_t s_aux;
    static cudaEvent_t ev_fork, ev_join;
    if (!init_done) {
        cudaFuncSetAttribute(gemm_qkvs_kernel,
                             cudaFuncAttributeMaxDynamicSharedMemorySize, GEMM_SMEM);
        cudaStreamCreateWithFlags(&s_aux, cudaStreamNonBlocking);
        cudaEventCreateWithFlags(&ev_fork, cudaEventDisableTiming);
        cudaEventCreateWithFlags(&ev_join, cudaEventDisableTiming);
        init_done = true;
    }

    const int SCAN_BLOCKS = (NN + 1023) / 1024;   // 49

    // fork: CSR build on aux stream, converts + GEMM0 on main stream
    cudaEventRecord(ev_fork, 0);
    cudaStreamWaitEvent(s_aux, ev_fork, 0);

    zero_counts_kernel<<<(NN + 255) / 256, 256, 0, s_aux>>>();
    count_dst_kernel<<<(EE + 255) / 256, 256, 0, s_aux>>>(ei);
    scan1_kernel<<<SCAN_BLOCKS, 1024, 0, s_aux>>>();
    scan2_kernel<<<1, 32, 0, s_aux>>>(SCAN_BLOCKS);
    scan3_kernel<<<SCAN_BLOCKS, 1024, 0, s_aux>>>();
    fill_csr_kernel<<<(EE + 255) / 256, 256, 0, s_aux>>>(ei);
    cudaEventRecord(ev_join, s_aux);

    convert_w_kernel<<<(LL * 4 * 65536 + 255) / 256, 256>>>(Wq, Wk, Wv, Ws, wh);
    convert_x_kernel<<<(NN * 256 + 255) / 256, 256>>>(x, ah);

    dim3 gemm_grid(8, (NN + BM - 1) / BM);
    int edge_blocks = (NN + 7) / 8;

    for (int l = 0; l < LL; l++) {
        gemm_qkvs_kernel<<<gemm_grid, 256, GEMM_SMEM>>>(
            ah, wh + (size_t)l * 4 * 65536,
            bq + l * HC, bk + l * HC, bv + l * HC, bs + l * HC,
            qs, kvp, NN);

        if (l == 0) cudaStreamWaitEvent(0, ev_join, 0);   // CSR ready before first edge pass

        float* hout = (l == LL - 1) ? out : nullptr;
        edge_attn_kernel<<<edge_blocks, 256>>>(qs, kvp, hout, ah);
    }
}